// round 2
// baseline (speedup 1.0000x reference)
#include <cuda_runtime.h>
#include <math.h>

#define BB 4
#define SS 256
#define VV 64
#define LL 11            // L+1
#define HH 128
#define NHH 8
#define DHH 16
#define NLL 3
#define BS (BB*SS)       // 1024
#define NROWS (BB*SS*VV) // 65536
#define KAB 80           // 64 (A) + 11 (Bl) + 5 pad

// ---------------- device scratch (static, no runtime allocation) ----------------
__device__ float g_adj[VV*VV*LL];
__device__ float g_E[KAB*HH];
__device__ float g_wf[VV*HH];
__device__ float g_bf[VV];
__device__ float g_AB[NROWS*KAB];
__device__ float g_z [NROWS*HH];
__device__ float g_z2[NROWS*HH];
__device__ float g_q [NROWS*HH];
__device__ float g_k [NROWS*HH];
__device__ float g_v [NROWS*HH];
__device__ float g_o [NROWS*HH];

// ---------------- prep: sigmoid(adj), E matrix, fused Wo*outW ----------------
__global__ void k_prep(const float* __restrict__ adjl,
                       const float* __restrict__ var_emb,
                       const float* __restrict__ temp_emb,
                       const float* __restrict__ Wo,
                       const float* __restrict__ outW,
                       const float* __restrict__ bo,
                       const float* __restrict__ outb) {
    int idx = blockIdx.x*blockDim.x + threadIdx.x;
    const int N_ADJ = VV*VV*LL;      // 45056
    const int N_E   = KAB*HH;        // 10240
    const int N_WF  = VV*HH;         // 8192
    if (idx < N_ADJ) {
        g_adj[idx] = 1.0f/(1.0f + __expf(-adjl[idx]));
    } else if (idx < N_ADJ + N_E) {
        int t = idx - N_ADJ;
        int j = t / HH, h = t % HH;
        float val = 0.0f;
        if (j < VV)          val = var_emb[j*HH + h];
        else if (j < VV+LL)  val = temp_emb[(j-VV)*HH + h];
        g_E[j*HH + h] = val;
    } else if (idx < N_ADJ + N_E + N_WF) {
        int t = idx - N_ADJ - N_E;
        int v = t / HH, h = t % HH;
        const float* wrow = Wo + (v*HH + h)*HH;
        const float* ow   = outW + v*HH;
        float acc = 0.0f;
        for (int k = 0; k < HH; k++) acc = fmaf(wrow[k], ow[k], acc);
        g_wf[v*HH + h] = acc;
    } else if (idx < N_ADJ + N_E + N_WF + VV) {
        int v = idx - N_ADJ - N_E - N_WF;
        float acc = outb[v];
        for (int k = 0; k < HH; k++) acc = fmaf(bo[v*HH+k], outW[v*HH+k], acc);
        g_bf[v] = acc;
    }
}

// ---------------- lag-mix: A[b,t,i,s], Bl[b,t,i,l] -> g_AB ----------------
__global__ void k_lagmix(const float* __restrict__ x) {
    extern __shared__ float sm[];
    float* x_sm   = sm;              // 256*64
    float* adj_sm = sm + SS*VV;      // 64*11
    int i = blockIdx.x & (VV-1);
    int b = blockIdx.x >> 6;
    int tid = threadIdx.x;

    const float4* xg = (const float4*)(x + b*SS*VV);
    float4* xs4 = (float4*)x_sm;
    for (int p = tid; p < SS*VV/4; p += 256) xs4[p] = xg[p];
    for (int p = tid; p < VV*LL; p += 256) {
        int s = p / LL, l = p % LL;
        adj_sm[p] = g_adj[(s*VV + i)*LL + l];
    }
    __syncthreads();

    // A part: thread = (s, t-group of 4)
    {
        int s  = tid & 63;
        int tg = tid >> 6;
        float a[LL];
        #pragma unroll
        for (int l = 0; l < LL; l++) a[l] = adj_sm[s*LL + l];
        for (int t = tg; t < SS; t += 4) {
            float acc = 0.0f;
            #pragma unroll
            for (int l = 0; l < LL; l++)
                if (t >= l) acc = fmaf(x_sm[(t-l)*VV + s], a[l], acc);
            g_AB[((b*SS + t)*VV + i)*KAB + s] = acc;
        }
    }
    // Bl part: warp-cooperative dot over s (conflict-free)
    {
        int w = tid >> 5, lane = tid & 31;
        for (int tt = 0; tt < 32; tt++) {
            int t = w*32 + tt;
            int rowbase = ((b*SS + t)*VV + i)*KAB;
            #pragma unroll
            for (int l = 0; l < LL; l++) {
                float p = 0.0f;
                if (t >= l) {
                    const float* xr = x_sm + (t-l)*VV;
                    p = xr[lane]      * adj_sm[lane*LL + l]
                      + xr[lane + 32] * adj_sm[(lane+32)*LL + l];
                }
                #pragma unroll
                for (int off = 16; off; off >>= 1) p += __shfl_xor_sync(0xffffffffu, p, off);
                if (lane == 0) g_AB[rowbase + VV + l] = p;
            }
            if (lane < (KAB - VV - LL)) g_AB[rowbase + VV + LL + lane] = 0.0f;
        }
    }
}

// ---------------- warp GEMM core: 4 rows x (4 cols/lane), K-loop from smem ----------------
template<int K>
__device__ __forceinline__ void warp_gemm4(const float* stg, const float4* W4, int lane,
                                           float4& a0, float4& a1, float4& a2, float4& a3) {
    const float4* s0 = (const float4*)(stg);
    const float4* s1 = (const float4*)(stg + K);
    const float4* s2 = (const float4*)(stg + 2*K);
    const float4* s3 = (const float4*)(stg + 3*K);
    #pragma unroll 4
    for (int k4 = 0; k4 < K/4; k4++) {
        float4 z0 = s0[k4], z1 = s1[k4], z2 = s2[k4], z3 = s3[k4];
        #pragma unroll
        for (int kk = 0; kk < 4; kk++) {
            float4 wv = W4[(k4*4 + kk)*32 + lane];
            float f0 = (kk==0)?z0.x:(kk==1)?z0.y:(kk==2)?z0.z:z0.w;
            float f1 = (kk==0)?z1.x:(kk==1)?z1.y:(kk==2)?z1.z:z1.w;
            float f2 = (kk==0)?z2.x:(kk==1)?z2.y:(kk==2)?z2.z:z2.w;
            float f3 = (kk==0)?z3.x:(kk==1)?z3.y:(kk==2)?z3.z:z3.w;
            a0.x = fmaf(f0, wv.x, a0.x); a0.y = fmaf(f0, wv.y, a0.y);
            a0.z = fmaf(f0, wv.z, a0.z); a0.w = fmaf(f0, wv.w, a0.w);
            a1.x = fmaf(f1, wv.x, a1.x); a1.y = fmaf(f1, wv.y, a1.y);
            a1.z = fmaf(f1, wv.z, a1.z); a1.w = fmaf(f1, wv.w, a1.w);
            a2.x = fmaf(f2, wv.x, a2.x); a2.y = fmaf(f2, wv.y, a2.y);
            a2.z = fmaf(f2, wv.z, a2.z); a2.w = fmaf(f2, wv.w, a2.w);
            a3.x = fmaf(f3, wv.x, a3.x); a3.y = fmaf(f3, wv.y, a3.y);
            a3.z = fmaf(f3, wv.z, a3.z); a3.w = fmaf(f3, wv.w, a3.w);
        }
    }
}

__device__ __forceinline__ void epi_store(float4 a, float4 bias, float4 g4, float4 be4,
                                          int doLN, float* outp, int lane) {
    a.x += bias.x; a.y += bias.y; a.z += bias.z; a.w += bias.w;
    if (doLN) {
        float s  = a.x + a.y + a.z + a.w;
        float ss = a.x*a.x + a.y*a.y + a.z*a.z + a.w*a.w;
        #pragma unroll
        for (int off = 16; off; off >>= 1) {
            s  += __shfl_xor_sync(0xffffffffu, s, off);
            ss += __shfl_xor_sync(0xffffffffu, ss, off);
        }
        const float inv = 1.0f/128.0f;
        float mu   = s*inv;
        float var  = ss*inv - mu*mu;
        float rstd = rsqrtf(var + 1e-5f);
        a.x = (a.x - mu)*rstd*g4.x + be4.x;
        a.y = (a.y - mu)*rstd*g4.y + be4.y;
        a.z = (a.z - mu)*rstd*g4.z + be4.z;
        a.w = (a.w - mu)*rstd*g4.w + be4.w;
        const float c = 0.70710678118654752440f;
        a.x = 0.5f*a.x*(1.0f + erff(a.x*c));
        a.y = 0.5f*a.y*(1.0f + erff(a.y*c));
        a.z = 0.5f*a.z*(1.0f + erff(a.z*c));
        a.w = 0.5f*a.w*(1.0f + erff(a.w*c));
    }
    ((float4*)outp)[lane] = a;
}

// ---------------- embedding GEMM: z = AB(65536x80) @ E(80x128) ----------------
__global__ void __launch_bounds__(256) k_embed() {
    extern __shared__ float sm[];
    float* Esm = sm;                 // 80*128
    float* stg = sm + KAB*HH;        // 8 warps * 4 rows * 80
    int tid = threadIdx.x, w = tid >> 5, lane = tid & 31;
    float4* E4 = (float4*)Esm;
    for (int p = tid; p < KAB*HH/4; p += 256) E4[p] = ((const float4*)g_E)[p];
    __syncthreads();
    int r0 = blockIdx.x*128 + w*16;
    float* mystg = stg + w*4*KAB;
    const float4 zero4 = make_float4(0,0,0,0);
    for (int m = 0; m < 4; m++) {
        int rb = r0 + m*4;
        __syncwarp();
        #pragma unroll
        for (int rr = 0; rr < 4; rr++)
            if (lane < KAB/4)
                ((float4*)(mystg + rr*KAB))[lane] = ((const float4*)(g_AB + (rb+rr)*KAB))[lane];
        __syncwarp();
        float4 a0 = zero4, a1 = zero4, a2 = zero4, a3 = zero4;
        warp_gemm4<KAB>(mystg, E4, lane, a0, a1, a2, a3);
        epi_store(a0, zero4, zero4, zero4, 0, g_z + (rb+0)*HH, lane);
        epi_store(a1, zero4, zero4, zero4, 0, g_z + (rb+1)*HH, lane);
        epi_store(a2, zero4, zero4, zero4, 0, g_z + (rb+2)*HH, lane);
        epi_store(a3, zero4, zero4, zero4, 0, g_z + (rb+3)*HH, lane);
    }
}

// ---------------- per-variable GEMM (+ bias [+ LN + GELU]) ----------------
__global__ void __launch_bounds__(256) k_pv(const float* __restrict__ in, float* __restrict__ out,
                     const float* __restrict__ Wbase, int wstride,
                     const float* __restrict__ bbase, int bstride,
                     const float* __restrict__ gbase, const float* __restrict__ betabase,
                     int doLN) {
    extern __shared__ float sm[];
    float* Wsm = sm;                 // 128*128
    float* stg = sm + HH*HH;         // 8 warps * 4 rows * 128
    int v = blockIdx.y;
    int tid = threadIdx.x, w = tid >> 5, lane = tid & 31;
    const float4* Wg = (const float4*)(Wbase + (size_t)v*wstride);
    float4* W4 = (float4*)Wsm;
    for (int p = tid; p < HH*HH/4; p += 256) W4[p] = Wg[p];
    __syncthreads();

    float4 bias = ((const float4*)(bbase + v*bstride))[lane];
    float4 g4 = make_float4(0,0,0,0), be4 = make_float4(0,0,0,0);
    if (doLN) {
        g4  = ((const float4*)(gbase   + v*bstride))[lane];
        be4 = ((const float4*)(betabase+ v*bstride))[lane];
    }

    int r0 = blockIdx.x*128 + w*16;   // row in (b*S+t) space
    float* mystg = stg + w*4*HH;
    const float4 zero4 = make_float4(0,0,0,0);
    for (int m = 0; m < 4; m++) {
        int rb = r0 + m*4;
        __syncwarp();
        #pragma unroll
        for (int rr = 0; rr < 4; rr++)
            ((float4*)(mystg + rr*HH))[lane] =
                ((const float4*)(in + ((rb+rr)*VV + v)*HH))[lane];
        __syncwarp();
        float4 a0 = zero4, a1 = zero4, a2 = zero4, a3 = zero4;
        warp_gemm4<HH>(mystg, W4, lane, a0, a1, a2, a3);
        epi_store(a0, bias, g4, be4, doLN, out + ((rb+0)*VV + v)*HH, lane);
        epi_store(a1, bias, g4, be4, doLN, out + ((rb+1)*VV + v)*HH, lane);
        epi_store(a2, bias, g4, be4, doLN, out + ((rb+2)*VV + v)*HH, lane);
        epi_store(a3, bias, g4, be4, doLN, out + ((rb+3)*VV + v)*HH, lane);
    }
}

// ---------------- attention per (b, v, head) ----------------
__global__ void __launch_bounds__(256, 2) k_attn() {
    __shared__ float Kt[DHH][SS+1];   // transposed, padded (conflict-free)
    __shared__ float Vt[DHH][SS+1];
    int bid  = blockIdx.x;
    int head = bid & (NHH-1);
    int v    = (bid >> 3) & (VV-1);
    int b    = bid >> 9;
    int tid  = threadIdx.x;
    int hbase = head*DHH;

    for (int pass = 0; pass < 16; pass++) {
        int t = pass*16 + (tid >> 4);
        int d = tid & 15;
        int gidx = ((b*SS + t)*VV + v)*HH + hbase + d;
        Kt[d][t] = g_k[gidx];
        Vt[d][t] = g_v[gidx];
    }
    __syncthreads();

    int w = tid >> 5, lane = tid & 31;
    for (int pass = 0; pass < 16; pass++) {
        int r0 = w*32 + pass*2;
        const float* q0p = g_q + ((b*SS + r0)*VV + v)*HH + hbase;
        const float* q1p = q0p + VV*HH;
        float q0[16], q1[16];
        #pragma unroll
        for (int d = 0; d < 16; d++) { q0[d] = __ldg(q0p + d); q1[d] = __ldg(q1p + d); }

        float sc0[8], sc1[8];
        #pragma unroll
        for (int jj = 0; jj < 8; jj++) {
            int j = jj*32 + lane;
            float s0 = 0.0f, s1 = 0.0f;
            #pragma unroll
            for (int d = 0; d < 16; d++) {
                float kv = Kt[d][j];
                s0 = fmaf(q0[d], kv, s0);
                s1 = fmaf(q1[d], kv, s1);
            }
            sc0[jj] = s0*0.25f; sc1[jj] = s1*0.25f;
        }
        float m0 = sc0[0], m1 = sc1[0];
        #pragma unroll
        for (int jj = 1; jj < 8; jj++) { m0 = fmaxf(m0, sc0[jj]); m1 = fmaxf(m1, sc1[jj]); }
        #pragma unroll
        for (int off = 16; off; off >>= 1) {
            m0 = fmaxf(m0, __shfl_xor_sync(0xffffffffu, m0, off));
            m1 = fmaxf(m1, __shfl_xor_sync(0xffffffffu, m1, off));
        }
        float sum0 = 0.0f, sum1 = 0.0f;
        #pragma unroll
        for (int jj = 0; jj < 8; jj++) {
            sc0[jj] = __expf(sc0[jj] - m0); sum0 += sc0[jj];
            sc1[jj] = __expf(sc1[jj] - m1); sum1 += sc1[jj];
        }
        #pragma unroll
        for (int off = 16; off; off >>= 1) {
            sum0 += __shfl_xor_sync(0xffffffffu, sum0, off);
            sum1 += __shfl_xor_sync(0xffffffffu, sum1, off);
        }
        float o0[16], o1[16];
        #pragma unroll
        for (int d = 0; d < 16; d++) { o0[d] = 0.0f; o1[d] = 0.0f; }
        #pragma unroll
        for (int jj = 0; jj < 8; jj++) {
            int j = jj*32 + lane;
            float p0 = sc0[jj], p1 = sc1[jj];
            #pragma unroll
            for (int d = 0; d < 16; d++) {
                float vv = Vt[d][j];
                o0[d] = fmaf(p0, vv, o0[d]);
                o1[d] = fmaf(p1, vv, o1[d]);
            }
        }
        #pragma unroll
        for (int d = 0; d < 16; d++) {
            #pragma unroll
            for (int off = 16; off; off >>= 1) {
                o0[d] += __shfl_xor_sync(0xffffffffu, o0[d], off);
                o1[d] += __shfl_xor_sync(0xffffffffu, o1[d], off);
            }
        }
        if (lane == 0) {
            float inv0 = 1.0f/sum0, inv1 = 1.0f/sum1;
            float* op0 = g_o + ((b*SS + r0)*VV + v)*HH + hbase;
            float* op1 = op0 + VV*HH;
            #pragma unroll
            for (int d4 = 0; d4 < 4; d4++) {
                ((float4*)op0)[d4] = make_float4(o0[4*d4]*inv0, o0[4*d4+1]*inv0,
                                                 o0[4*d4+2]*inv0, o0[4*d4+3]*inv0);
                ((float4*)op1)[d4] = make_float4(o1[4*d4]*inv1, o1[4*d4+1]*inv1,
                                                 o1[4*d4+2]*inv1, o1[4*d4+3]*inv1);
            }
        }
    }
}

// ---------------- output head: pred = o . wf[v] + bf[v] ----------------
__global__ void k_out(float* __restrict__ out) {
    int w = threadIdx.x >> 5, lane = threadIdx.x & 31;
    int r = blockIdx.x*8 + w;
    int v = r & (VV-1);
    float4 o4 = ((const float4*)(g_o  + r*HH))[lane];
    float4 w4 = ((const float4*)(g_wf + v*HH))[lane];
    float p = o4.x*w4.x + o4.y*w4.y + o4.z*w4.z + o4.w*w4.w;
    #pragma unroll
    for (int off = 16; off; off >>= 1) p += __shfl_xor_sync(0xffffffffu, p, off);
    if (lane == 0) out[r] = p + g_bf[v];
}

// ---------------- launch ----------------
extern "C" void kernel_launch(void* const* d_in, const int* in_sizes, int n_in,
                              void* d_out, int out_size) {
    (void)in_sizes; (void)n_in; (void)out_size;
    const float* x        = (const float*)d_in[0];
    const float* adjl     = (const float*)d_in[1];
    const float* var_emb  = (const float*)d_in[2];
    const float* temp_emb = (const float*)d_in[3];
    const float* mech_W   = (const float*)d_in[4];
    const float* mech_b   = (const float*)d_in[5];
    const float* ln_g     = (const float*)d_in[6];
    const float* ln_b     = (const float*)d_in[7];
    const float* Wq       = (const float*)d_in[8];
    const float* Wk       = (const float*)d_in[9];
    const float* Wv       = (const float*)d_in[10];
    const float* Wo       = (const float*)d_in[11];
    const float* bq       = (const float*)d_in[12];
    const float* bk       = (const float*)d_in[13];
    const float* bv       = (const float*)d_in[14];
    const float* bo       = (const float*)d_in[15];
    const float* outW     = (const float*)d_in[16];
    const float* outb     = (const float*)d_in[17];
    float* out = (float*)d_out;

    const int SMEM_LAG = (SS*VV + VV*LL)*4;            // 68352
    const int SMEM_EMB = (KAB*HH + 8*4*KAB)*4;         // 51200
    const int SMEM_PV  = (HH*HH + 8*4*HH)*4;           // 81920
    cudaFuncSetAttribute(k_lagmix, cudaFuncAttributeMaxDynamicSharedMemorySize, SMEM_LAG);
    cudaFuncSetAttribute(k_embed,  cudaFuncAttributeMaxDynamicSharedMemorySize, SMEM_EMB);
    cudaFuncSetAttribute(k_pv,     cudaFuncAttributeMaxDynamicSharedMemorySize, SMEM_PV);

    float *pz, *pz2, *pq, *pk, *pvv;
    cudaGetSymbolAddress((void**)&pz,  g_z);
    cudaGetSymbolAddress((void**)&pz2, g_z2);
    cudaGetSymbolAddress((void**)&pq,  g_q);
    cudaGetSymbolAddress((void**)&pk,  g_k);
    cudaGetSymbolAddress((void**)&pvv, g_v);

    k_prep<<<(63552 + 255)/256, 256>>>(adjl, var_emb, temp_emb, Wo, outW, bo, outb);
    k_lagmix<<<BB*VV, 256, SMEM_LAG>>>(x);
    k_embed<<<NROWS/128, 256, SMEM_EMB>>>();

    dim3 gpv(BS/128, VV);
    // 3 mech layers (ping-pong z <-> z2), LN+GELU epilogue
    k_pv<<<gpv, 256, SMEM_PV>>>(pz,  pz2, mech_W + 0*HH*HH, NLL*HH*HH, mech_b + 0*HH, NLL*HH,
                                ln_g + 0*HH, ln_b + 0*HH, 1);
    k_pv<<<gpv, 256, SMEM_PV>>>(pz2, pz,  mech_W + 1*HH*HH, NLL*HH*HH, mech_b + 1*HH, NLL*HH,
                                ln_g + 1*HH, ln_b + 1*HH, 1);
    k_pv<<<gpv, 256, SMEM_PV>>>(pz,  pz2, mech_W + 2*HH*HH, NLL*HH*HH, mech_b + 2*HH, NLL*HH,
                                ln_g + 2*HH, ln_b + 2*HH, 1);
    // QKV projections (bias only)
    k_pv<<<gpv, 256, SMEM_PV>>>(pz2, pq,  Wq, HH*HH, bq, HH, nullptr, nullptr, 0);
    k_pv<<<gpv, 256, SMEM_PV>>>(pz2, pk,  Wk, HH*HH, bk, HH, nullptr, nullptr, 0);
    k_pv<<<gpv, 256, SMEM_PV>>>(pz2, pvv, Wv, HH*HH, bv, HH, nullptr, nullptr, 0);

    k_attn<<<BB*VV*NHH, 256>>>();
    k_out<<<NROWS/8, 256>>>(out);
}

// round 8
// speedup vs baseline: 1.2943x; 1.2943x over previous
#include <cuda_runtime.h>
#include <math.h>
#include <stdint.h>

#define BB 4
#define SS 256
#define VV 64
#define LL 11            // L+1
#define HH 128
#define NHH 8
#define DHH 16
#define NLL 3
#define BS (BB*SS)       // 1024
#define NROWS (BB*SS*VV) // 65536
#define KAB 80           // 64 (A) + 11 (Bl) + 5 pad

// smem pitches (floats) chosen for conflict-free mma fragment access
#define PW 136           // Wsm: bank = 8n + k  -> distinct over (n:8, k:4)
#define PZ 132           // Zsm: bank = 4m + k  -> distinct over (m:8, k:4)

// ---------------- device scratch ----------------
__device__ float g_adj[VV*VV*LL];
__device__ float g_E[KAB*HH];
__device__ float g_wf[VV*HH];
__device__ float g_bf[VV];
__device__ float g_AB[NROWS*KAB];
__device__ float g_z [NROWS*HH];
__device__ float g_q [NROWS*HH];
__device__ float g_k [NROWS*HH];
__device__ float g_v [NROWS*HH];
__device__ float g_o [NROWS*HH];
// transposed (W^T[n][k]) + tf32-rounded weights: [6 mats][64 v][128*128]
__device__ float g_Wt[6*VV*HH*HH];

// ---------------- helpers ----------------
__device__ __forceinline__ uint32_t f2tf32(float x) {
    uint32_t r; asm("cvt.rna.tf32.f32 %0, %1;" : "=r"(r) : "f"(x)); return r;
}
__device__ __forceinline__ void mma_tf32(float* c, const uint32_t* a, const uint32_t* b) {
    asm volatile(
        "mma.sync.aligned.m16n8k8.row.col.f32.tf32.tf32.f32 "
        "{%0,%1,%2,%3}, {%4,%5,%6,%7}, {%8,%9}, {%0,%1,%2,%3};"
        : "+f"(c[0]), "+f"(c[1]), "+f"(c[2]), "+f"(c[3])
        : "r"(a[0]), "r"(a[1]), "r"(a[2]), "r"(a[3]), "r"(b[0]), "r"(b[1]));
}

// ---------------- prep: sigmoid(adj), E matrix, fused Wo*outW ----------------
__global__ void k_prep(const float* __restrict__ adjl,
                       const float* __restrict__ var_emb,
                       const float* __restrict__ temp_emb,
                       const float* __restrict__ Wo,
                       const float* __restrict__ outW,
                       const float* __restrict__ bo,
                       const float* __restrict__ outb) {
    int idx = blockIdx.x*blockDim.x + threadIdx.x;
    const int N_ADJ = VV*VV*LL;
    const int N_E   = KAB*HH;
    const int N_WF  = VV*HH;
    if (idx < N_ADJ) {
        g_adj[idx] = 1.0f/(1.0f + __expf(-adjl[idx]));
    } else if (idx < N_ADJ + N_E) {
        int t = idx - N_ADJ;
        int j = t / HH, h = t % HH;
        float val = 0.0f;
        if (j < VV)          val = var_emb[j*HH + h];
        else if (j < VV+LL)  val = temp_emb[(j-VV)*HH + h];
        g_E[j*HH + h] = val;
    } else if (idx < N_ADJ + N_E + N_WF) {
        int t = idx - N_ADJ - N_E;
        int v = t / HH, h = t % HH;
        const float* wrow = Wo + (v*HH + h)*HH;
        const float* ow   = outW + v*HH;
        float acc = 0.0f;
        for (int k = 0; k < HH; k++) acc = fmaf(wrow[k], ow[k], acc);
        g_wf[v*HH + h] = acc;
    } else if (idx < N_ADJ + N_E + N_WF + VV) {
        int v = idx - N_ADJ - N_E - N_WF;
        float acc = outb[v];
        for (int k = 0; k < HH; k++) acc = fmaf(bo[v*HH+k], outW[v*HH+k], acc);
        g_bf[v] = acc;
    }
}

// ---------------- transpose + tf32-round the 6 weight sets: g_Wt[n][k] = W[k][n] ----------------
__global__ void __launch_bounds__(256) k_transpose(const float* __restrict__ mechW,
        const float* __restrict__ Wq, const float* __restrict__ Wk, const float* __restrict__ Wv) {
    extern __shared__ float sm[];     // 128 x 129 floats
    int mat = blockIdx.x >> 6;        // 0..5
    int v   = blockIdx.x & 63;
    const float* src;
    if (mat < 3)       src = mechW + ((size_t)v*NLL + mat)*HH*HH;
    else if (mat == 3) src = Wq + (size_t)v*HH*HH;
    else if (mat == 4) src = Wk + (size_t)v*HH*HH;
    else               src = Wv + (size_t)v*HH*HH;
    float* dst = g_Wt + ((size_t)mat*VV + v)*HH*HH;
    int tid = threadIdx.x;
    // load W[k][n] into sm[k*129 + n] (coalesced global, conflict-free smem)
    for (int idx = tid; idx < HH*HH/4; idx += 256) {
        int k = idx >> 5, c4 = idx & 31;
        float4 w = ((const float4*)src)[idx];
        float* p = sm + k*129 + 4*c4;
        p[0]=w.x; p[1]=w.y; p[2]=w.z; p[3]=w.w;
    }
    __syncthreads();
    // write W^T[n][k] tf32-rounded (reads bank=(k+n), conflict-free; writes coalesced)
    for (int idx = tid; idx < HH*HH/4; idx += 256) {
        int n = idx >> 5, k4 = idx & 31;
        int k = 4*k4;
        uint4 u;
        u.x = f2tf32(sm[(k+0)*129 + n]);
        u.y = f2tf32(sm[(k+1)*129 + n]);
        u.z = f2tf32(sm[(k+2)*129 + n]);
        u.w = f2tf32(sm[(k+3)*129 + n]);
        ((uint4*)(dst + n*HH))[k4] = u;
    }
}

// ---------------- lag-mix (unchanged, proven) ----------------
__global__ void k_lagmix(const float* __restrict__ x) {
    extern __shared__ float sm[];
    float* x_sm   = sm;
    float* adj_sm = sm + SS*VV;
    int i = blockIdx.x & (VV-1);
    int b = blockIdx.x >> 6;
    int tid = threadIdx.x;

    const float4* xg = (const float4*)(x + b*SS*VV);
    float4* xs4 = (float4*)x_sm;
    for (int p = tid; p < SS*VV/4; p += 256) xs4[p] = xg[p];
    for (int p = tid; p < VV*LL; p += 256) {
        int s = p / LL, l = p % LL;
        adj_sm[p] = g_adj[(s*VV + i)*LL + l];
    }
    __syncthreads();
    {
        int s  = tid & 63;
        int tg = tid >> 6;
        float a[LL];
        #pragma unroll
        for (int l = 0; l < LL; l++) a[l] = adj_sm[s*LL + l];
        for (int t = tg; t < SS; t += 4) {
            float acc = 0.0f;
            #pragma unroll
            for (int l = 0; l < LL; l++)
                if (t >= l) acc = fmaf(x_sm[(t-l)*VV + s], a[l], acc);
            g_AB[((b*SS + t)*VV + i)*KAB + s] = acc;
        }
    }
    {
        int w = tid >> 5, lane = tid & 31;
        for (int tt = 0; tt < 32; tt++) {
            int t = w*32 + tt;
            int rowbase = ((b*SS + t)*VV + i)*KAB;
            #pragma unroll
            for (int l = 0; l < LL; l++) {
                float p = 0.0f;
                if (t >= l) {
                    const float* xr = x_sm + (t-l)*VV;
                    p = xr[lane]      * adj_sm[lane*LL + l]
                      + xr[lane + 32] * adj_sm[(lane+32)*LL + l];
                }
                #pragma unroll
                for (int off = 16; off; off >>= 1) p += __shfl_xor_sync(0xffffffffu, p, off);
                if (lane == 0) g_AB[rowbase + VV + l] = p;
            }
            if (lane < (KAB - VV - LL)) g_AB[rowbase + VV + LL + lane] = 0.0f;
        }
    }
}

// ---------------- fp32 warp GEMM (embed only, proven) ----------------
template<int K>
__device__ __forceinline__ void warp_gemm4(const float* stg, const float4* W4, int lane,
                                           float4& a0, float4& a1, float4& a2, float4& a3) {
    const float4* s0 = (const float4*)(stg);
    const float4* s1 = (const float4*)(stg + K);
    const float4* s2 = (const float4*)(stg + 2*K);
    const float4* s3 = (const float4*)(stg + 3*K);
    #pragma unroll 4
    for (int k4 = 0; k4 < K/4; k4++) {
        float4 z0 = s0[k4], z1 = s1[k4], z2 = s2[k4], z3 = s3[k4];
        #pragma unroll
        for (int kk = 0; kk < 4; kk++) {
            float4 wv = W4[(k4*4 + kk)*32 + lane];
            float f0 = (kk==0)?z0.x:(kk==1)?z0.y:(kk==2)?z0.z:z0.w;
            float f1 = (kk==0)?z1.x:(kk==1)?z1.y:(kk==2)?z1.z:z1.w;
            float f2 = (kk==0)?z2.x:(kk==1)?z2.y:(kk==2)?z2.z:z2.w;
            float f3 = (kk==0)?z3.x:(kk==1)?z3.y:(kk==2)?z3.z:z3.w;
            a0.x = fmaf(f0, wv.x, a0.x); a0.y = fmaf(f0, wv.y, a0.y);
            a0.z = fmaf(f0, wv.z, a0.z); a0.w = fmaf(f0, wv.w, a0.w);
            a1.x = fmaf(f1, wv.x, a1.x); a1.y = fmaf(f1, wv.y, a1.y);
            a1.z = fmaf(f1, wv.z, a1.z); a1.w = fmaf(f1, wv.w, a1.w);
            a2.x = fmaf(f2, wv.x, a2.x); a2.y = fmaf(f2, wv.y, a2.y);
            a2.z = fmaf(f2, wv.z, a2.z); a2.w = fmaf(f2, wv.w, a2.w);
            a3.x = fmaf(f3, wv.x, a3.x); a3.y = fmaf(f3, wv.y, a3.y);
            a3.z = fmaf(f3, wv.z, a3.z); a3.w = fmaf(f3, wv.w, a3.w);
        }
    }
}

// ---------------- embedding GEMM: z = AB(65536x80) @ E(80x128) ----------------
__global__ void __launch_bounds__(256) k_embed() {
    extern __shared__ float sm[];
    float* Esm = sm;
    float* stg = sm + KAB*HH;
    int tid = threadIdx.x, w = tid >> 5, lane = tid & 31;
    float4* E4 = (float4*)Esm;
    for (int p = tid; p < KAB*HH/4; p += 256) E4[p] = ((const float4*)g_E)[p];
    __syncthreads();
    int r0 = blockIdx.x*128 + w*16;
    float* mystg = stg + w*4*KAB;
    const float4 zero4 = make_float4(0,0,0,0);
    for (int m = 0; m < 4; m++) {
        int rb = r0 + m*4;
        __syncwarp();
        #pragma unroll
        for (int rr = 0; rr < 4; rr++)
            if (lane < KAB/4)
                ((float4*)(mystg + rr*KAB))[lane] = ((const float4*)(g_AB + (rb+rr)*KAB))[lane];
        __syncwarp();
        float4 a0 = zero4, a1 = zero4, a2 = zero4, a3 = zero4;
        warp_gemm4<KAB>(mystg, E4, lane, a0, a1, a2, a3);
        ((float4*)(g_z + (rb+0)*HH))[lane] = a0;
        ((float4*)(g_z + (rb+1)*HH))[lane] = a1;
        ((float4*)(g_z + (rb+2)*HH))[lane] = a2;
        ((float4*)(g_z + (rb+3)*HH))[lane] = a3;
    }
}

// ---------------- fused mech x3 + QKV chain via mma.sync tf32 ----------------
// CTA = (row-tile of 128, variable v); 256 threads (8 warps).
// Computes out^T[n][m] = W^T[n][k] * z[m][k] -> C' staged in (freed) Wsm region.
// Warp w: n-range = (w&1)*64 .. +64, m-range = (w>>1)*32 .. +32.
__global__ void __launch_bounds__(256, 1) k_chain(const float* __restrict__ mech_b,
        const float* __restrict__ ln_g, const float* __restrict__ ln_b,
        const float* __restrict__ bqv, const float* __restrict__ bkv,
        const float* __restrict__ bvv) {
    extern __shared__ float smf[];
    float* Wsm = smf;                         // 128 x PW floats (also C' staging)
    float* Zsm = smf + HH*PW;                 // 128 x PZ floats
    float* bias_sm = smf + HH*PW + HH*PZ;     // 128
    float* g_sm    = bias_sm + HH;            // 128
    float* be_sm   = g_sm + HH;               // 128
    uint32_t* Wu = (uint32_t*)Wsm;
    uint32_t* Zu = (uint32_t*)Zsm;

    int tid  = threadIdx.x;
    int w    = tid >> 5, lane = tid & 31;
    int gid  = lane >> 2, qid = lane & 3;     // groupID, threadID-in-group
    int v    = blockIdx.y;
    int r0   = blockIdx.x * 128;
    int n0   = (w & 1) * 64;
    int m0   = (w >> 1) * 32;

    // ---- initial Zsm fill from g_z: warp-per-row, tf32-rounded ----
    for (int it = 0; it < 16; it++) {
        int m = w + 8*it;
        float4 zv = ((const float4*)(g_z + ((size_t)(r0+m)*VV + v)*HH))[lane];
        uint4 u; u.x=f2tf32(zv.x); u.y=f2tf32(zv.y); u.z=f2tf32(zv.z); u.w=f2tf32(zv.w);
        ((uint4*)(Zu + m*PZ))[lane] = u;
    }

    #pragma unroll 1
    for (int phase = 0; phase < 6; phase++) {
        __syncthreads();   // Zsm writes / previous-phase Cstg reads done
        // ---- load W^T[n][k] into Wsm (pitch PW) ----
        {
            const float4* src = (const float4*)(g_Wt + ((size_t)phase*VV + v)*HH*HH);
            #pragma unroll
            for (int i = 0; i < 16; i++) {
                int idx = tid + 256*i;
                int n = idx >> 5, k4 = idx & 31;
                ((float4*)(Wsm + n*PW))[k4] = src[idx];
            }
        }
        // ---- per-phase bias / LN params ----
        if (tid < HH) {
            if (phase < 3) {
                bias_sm[tid] = mech_b[((size_t)v*NLL + phase)*HH + tid];
                g_sm[tid]    = ln_g  [((size_t)v*NLL + phase)*HH + tid];
                be_sm[tid]   = ln_b  [((size_t)v*NLL + phase)*HH + tid];
            } else {
                const float* bp = (phase == 3) ? bqv : (phase == 4) ? bkv : bvv;
                bias_sm[tid] = bp[v*HH + tid];
            }
        }
        __syncthreads();

        // ---- mma mainloop ----
        float acc[4][4][4];
        #pragma unroll
        for (int nt = 0; nt < 4; nt++)
            #pragma unroll
            for (int mt = 0; mt < 4; mt++)
                #pragma unroll
                for (int r = 0; r < 4; r++) acc[nt][mt][r] = 0.0f;

        #pragma unroll 4
        for (int s = 0; s < 16; s++) {
            int k0 = 8*s;
            uint32_t Af[4][4], Bf[4][2];
            #pragma unroll
            for (int nt = 0; nt < 4; nt++) {
                const uint32_t* p = Wu + (n0 + nt*16 + gid)*PW + k0 + qid;
                Af[nt][0] = p[0];
                Af[nt][1] = p[8*PW];
                Af[nt][2] = p[4];
                Af[nt][3] = p[8*PW + 4];
            }
            #pragma unroll
            for (int mt = 0; mt < 4; mt++) {
                const uint32_t* q = Zu + (m0 + mt*8 + gid)*PZ + k0 + qid;
                Bf[mt][0] = q[0];
                Bf[mt][1] = q[4];
            }
            #pragma unroll
            for (int nt = 0; nt < 4; nt++)
                #pragma unroll
                for (int mt = 0; mt < 4; mt++)
                    mma_tf32(acc[nt][mt], Af[nt], Bf[mt]);
        }
        __syncthreads();   // all warps done reading Wsm -> reuse as Cstg[m][n] (pitch PW)

        // ---- stage C' fragments: Cstg[m][n] ----
        #pragma unroll
        for (int nt = 0; nt < 4; nt++) {
            int nb = n0 + nt*16 + gid;
            #pragma unroll
            for (int mt = 0; mt < 4; mt++) {
                int mb = m0 + mt*8 + 2*qid;
                Wsm[ mb   *PW + nb    ] = acc[nt][mt][0];
                Wsm[(mb+1)*PW + nb    ] = acc[nt][mt][1];
                Wsm[ mb   *PW + nb + 8] = acc[nt][mt][2];
                Wsm[(mb+1)*PW + nb + 8] = acc[nt][mt][3];
            }
        }
        __syncthreads();

        // ---- epilogue: warp-per-row ----
        if (phase < 3) {
            for (int it = 0; it < 16; it++) {
                int m = w + 8*it;
                float4 c = ((const float4*)(Wsm + m*PW))[lane];
                float4 b4 = ((const float4*)bias_sm)[lane];
                c.x += b4.x; c.y += b4.y; c.z += b4.z; c.w += b4.w;
                float s  = c.x + c.y + c.z + c.w;
                float ss = c.x*c.x + c.y*c.y + c.z*c.z + c.w*c.w;
                #pragma unroll
                for (int off = 16; off; off >>= 1) {
                    s  += __shfl_xor_sync(0xffffffffu, s,  off);
                    ss += __shfl_xor_sync(0xffffffffu, ss, off);
                }
                float mu   = s * (1.0f/128.0f);
                float var  = ss * (1.0f/128.0f) - mu*mu;
                float rstd = rsqrtf(var + 1e-5f);
                float4 g4  = ((const float4*)g_sm)[lane];
                float4 be4 = ((const float4*)be_sm)[lane];
                const float ic = 0.70710678118654752440f;
                float y;
                uint4 u;
                y = (c.x - mu)*rstd*g4.x + be4.x; y = 0.5f*y*(1.0f + erff(y*ic)); u.x = f2tf32(y);
                y = (c.y - mu)*rstd*g4.y + be4.y; y = 0.5f*y*(1.0f + erff(y*ic)); u.y = f2tf32(y);
                y = (c.z - mu)*rstd*g4.z + be4.z; y = 0.5f*y*(1.0f + erff(y*ic)); u.z = f2tf32(y);
                y = (c.w - mu)*rstd*g4.w + be4.w; y = 0.5f*y*(1.0f + erff(y*ic)); u.w = f2tf32(y);
                ((uint4*)(Zu + m*PZ))[lane] = u;
            }
        } else {
            float* outp = (phase == 3) ? g_q : (phase == 4) ? g_k : g_v;
            for (int it = 0; it < 16; it++) {
                int m = w + 8*it;
                float4 c = ((const float4*)(Wsm + m*PW))[lane];
                float4 b4 = ((const float4*)bias_sm)[lane];
                c.x += b4.x; c.y += b4.y; c.z += b4.z; c.w += b4.w;
                ((float4*)(outp + ((size_t)(r0+m)*VV + v)*HH))[lane] = c;
            }
        }
    }
}

// ---------------- attention per (b, v, head) (unchanged, proven) ----------------
__global__ void __launch_bounds__(256, 2) k_attn() {
    __shared__ float Kt[DHH][SS+1];
    __shared__ float Vt[DHH][SS+1];
    int bid  = blockIdx.x;
    int head = bid & (NHH-1);
    int v    = (bid >> 3) & (VV-1);
    int b    = bid >> 9;
    int tid  = threadIdx.x;
    int hbase = head*DHH;

    for (int pass = 0; pass < 16; pass++) {
        int t = pass*16 + (tid >> 4);
        int d = tid & 15;
        int gidx = ((b*SS + t)*VV + v)*HH + hbase + d;
        Kt[d][t] = g_k[gidx];
        Vt[d][t] = g_v[gidx];
    }
    __syncthreads();

    int w = tid >> 5, lane = tid & 31;
    for (int pass = 0; pass < 16; pass++) {
        int r0 = w*32 + pass*2;
        const float* q0p = g_q + ((b*SS + r0)*VV + v)*HH + hbase;
        const float* q1p = q0p + VV*HH;
        float q0[16], q1[16];
        #pragma unroll
        for (int d = 0; d < 16; d++) { q0[d] = __ldg(q0p + d); q1[d] = __ldg(q1p + d); }

        float sc0[8], sc1[8];
        #pragma unroll
        for (int jj = 0; jj < 8; jj++) {
            int j = jj*32 + lane;
            float s0 = 0.0f, s1 = 0.0f;
            #pragma unroll
            for (int d = 0; d < 16; d++) {
                float kv = Kt[d][j];
                s0 = fmaf(q0[d], kv, s0);
                s1 = fmaf(q1[d], kv, s1);
            }
            sc0[jj] = s0*0.25f; sc1[jj] = s1*0.25f;
        }
        float m0 = sc0[0], m1 = sc1[0];
        #pragma unroll
        for (int jj = 1; jj < 8; jj++) { m0 = fmaxf(m0, sc0[jj]); m1 = fmaxf(m1, sc1[jj]); }
        #pragma unroll
        for (int off = 16; off; off >>= 1) {
            m0 = fmaxf(m0, __shfl_xor_sync(0xffffffffu, m0, off));
            m1 = fmaxf(m1, __shfl_xor_sync(0xffffffffu, m1, off));
        }
        float sum0 = 0.0f, sum1 = 0.0f;
        #pragma unroll
        for (int jj = 0; jj < 8; jj++) {
            sc0[jj] = __expf(sc0[jj] - m0); sum0 += sc0[jj];
            sc1[jj] = __expf(sc1[jj] - m1); sum1 += sc1[jj];
        }
        #pragma unroll
        for (int off = 16; off; off >>= 1) {
            sum0 += __shfl_xor_sync(0xffffffffu, sum0, off);
            sum1 += __shfl_xor_sync(0xffffffffu, sum1, off);
        }
        float o0[16], o1[16];
        #pragma unroll
        for (int d = 0; d < 16; d++) { o0[d] = 0.0f; o1[d] = 0.0f; }
        #pragma unroll
        for (int jj = 0; jj < 8; jj++) {
            int j = jj*32 + lane;
            float p0 = sc0[jj], p1 = sc1[jj];
            #pragma unroll
            for (int d = 0; d < 16; d++) {
                float vv = Vt[d][j];
                o0[d] = fmaf(p0, vv, o0[d]);
                o1[d] = fmaf(p1, vv, o1[d]);
            }
        }
        #pragma unroll
        for (int d = 0; d < 16; d++) {
            #pragma unroll
            for (int off = 16; off; off >>= 1) {
                o0[d] += __shfl_xor_sync(0xffffffffu, o0[d], off);
                o1[d] += __shfl_xor_sync(0xffffffffu, o1[d], off);
            }
        }
        if (lane == 0) {
            float inv0 = 1.0f/sum0, inv1 = 1.0f/sum1;
            float* op0 = g_o + ((b*SS + r0)*VV + v)*HH + hbase;
            float* op1 = op0 + VV*HH;
            #pragma unroll
            for (int d4 = 0; d4 < 4; d4++) {
                ((float4*)op0)[d4] = make_float4(o0[4*d4]*inv0, o0[4*d4+1]*inv0,
                                                 o0[4*d4+2]*inv0, o0[4*d4+3]*inv0);
                ((float4*)op1)[d4] = make_float4(o1[4*d4]*inv1, o1[4*d4+1]*inv1,
                                                 o1[4*d4+2]*inv1, o1[4*d4+3]*inv1);
            }
        }
    }
}

// ---------------- output head ----------------
__global__ void k_out(float* __restrict__ out) {
    int w = threadIdx.x >> 5, lane = threadIdx.x & 31;
    int r = blockIdx.x*8 + w;
    int v = r & (VV-1);
    float4 o4 = ((const float4*)(g_o  + r*HH))[lane];
    float4 w4 = ((const float4*)(g_wf + v*HH))[lane];
    float p = o4.x*w4.x + o4.y*w4.y + o4.z*w4.z + o4.w*w4.w;
    #pragma unroll
    for (int off = 16; off; off >>= 1) p += __shfl_xor_sync(0xffffffffu, p, off);
    if (lane == 0) out[r] = p + g_bf[v];
}

// ---------------- launch ----------------
extern "C" void kernel_launch(void* const* d_in, const int* in_sizes, int n_in,
                              void* d_out, int out_size) {
    (void)in_sizes; (void)n_in; (void)out_size;
    const float* x        = (const float*)d_in[0];
    const float* adjl     = (const float*)d_in[1];
    const float* var_emb  = (const float*)d_in[2];
    const float* temp_emb = (const float*)d_in[3];
    const float* mech_W   = (const float*)d_in[4];
    const float* mech_b   = (const float*)d_in[5];
    const float* ln_g     = (const float*)d_in[6];
    const float* ln_b     = (const float*)d_in[7];
    const float* Wq       = (const float*)d_in[8];
    const float* Wk       = (const float*)d_in[9];
    const float* Wv       = (const float*)d_in[10];
    const float* Wo       = (const float*)d_in[11];
    const float* bq       = (const float*)d_in[12];
    const float* bk       = (const float*)d_in[13];
    const float* bv       = (const float*)d_in[14];
    const float* bo       = (const float*)d_in[15];
    const float* outW     = (const float*)d_in[16];
    const float* outb     = (const float*)d_in[17];
    float* out = (float*)d_out;

    const int SMEM_LAG   = (SS*VV + VV*LL)*4;
    const int SMEM_EMB   = (KAB*HH + 8*4*KAB)*4;
    const int SMEM_TRANS = HH*129*4;                   // 66048
    const int SMEM_CHAIN = (HH*PW + HH*PZ + 3*HH)*4;   // 138752
    cudaFuncSetAttribute(k_lagmix,    cudaFuncAttributeMaxDynamicSharedMemorySize, SMEM_LAG);
    cudaFuncSetAttribute(k_embed,     cudaFuncAttributeMaxDynamicSharedMemorySize, SMEM_EMB);
    cudaFuncSetAttribute(k_transpose, cudaFuncAttributeMaxDynamicSharedMemorySize, SMEM_TRANS);
    cudaFuncSetAttribute(k_chain,     cudaFuncAttributeMaxDynamicSharedMemorySize, SMEM_CHAIN);

    k_prep<<<(63552 + 255)/256, 256>>>(adjl, var_emb, temp_emb, Wo, outW, bo, outb);
    k_transpose<<<6*VV, 256, SMEM_TRANS>>>(mech_W, Wq, Wk, Wv);
    k_lagmix<<<BB*VV, 256, SMEM_LAG>>>(x);
    k_embed<<<NROWS/128, 256, SMEM_EMB>>>();

    dim3 gchain(BS/128, VV);   // (8, 64)
    k_chain<<<gchain, 256, SMEM_CHAIN>>>(mech_b, ln_g, ln_b, bq, bk, bv);

    k_attn<<<BB*VV*NHH, 256>>>();
    k_out<<<NROWS/8, 256>>>(out);
}

// round 13
// speedup vs baseline: 2.0123x; 1.5546x over previous
#include <cuda_runtime.h>
#include <math.h>
#include <stdint.h>

#define BB 4
#define SS 256
#define VV 64
#define LL 11            // L+1
#define HH 128
#define NHH 8
#define DHH 16
#define NLL 3
#define BS (BB*SS)       // 1024
#define NROWS (BB*SS*VV) // 65536
#define KAB 80           // 64 (A) + 11 (Bl) + 5 pad

// smem pitches (floats) chosen for conflict-free mma fragment access
#define PW 136           // Wsm: bank = 8n + k  -> distinct over (n:8, k:4)
#define PZ 132           // Zsm: bank = 4m + k  -> distinct over (m:8, k:4)
#define PK 20            // attn K: bank = 20*gid + qid -> all 32 distinct
#define PVT 24           // attn V: bank = 24*qid + gid -> all 32 distinct

// ---------------- device scratch ----------------
__device__ float g_adj[VV*VV*LL];
__device__ float g_E[KAB*HH];
__device__ float g_wf[VV*HH];
__device__ float g_bf[VV];
__device__ float g_AB[NROWS*KAB];
__device__ float g_z [NROWS*HH];
__device__ float g_q [NROWS*HH];
__device__ float g_k [NROWS*HH];
__device__ float g_v [NROWS*HH];
__device__ float g_o [NROWS*HH];
// transposed (W^T[n][k]) + tf32-rounded weights: [6 mats][64 v][128*128]
__device__ float g_Wt[6*VV*HH*HH];

// ---------------- helpers ----------------
__device__ __forceinline__ uint32_t f2tf32(float x) {
    uint32_t r; asm("cvt.rna.tf32.f32 %0, %1;" : "=r"(r) : "f"(x)); return r;
}
__device__ __forceinline__ void mma_tf32(float* c, const uint32_t* a, const uint32_t* b) {
    asm volatile(
        "mma.sync.aligned.m16n8k8.row.col.f32.tf32.tf32.f32 "
        "{%0,%1,%2,%3}, {%4,%5,%6,%7}, {%8,%9}, {%0,%1,%2,%3};"
        : "+f"(c[0]), "+f"(c[1]), "+f"(c[2]), "+f"(c[3])
        : "r"(a[0]), "r"(a[1]), "r"(a[2]), "r"(a[3]), "r"(b[0]), "r"(b[1]));
}

// ---------------- prep: sigmoid(adj), E matrix, fused Wo*outW ----------------
__global__ void k_prep(const float* __restrict__ adjl,
                       const float* __restrict__ var_emb,
                       const float* __restrict__ temp_emb,
                       const float* __restrict__ Wo,
                       const float* __restrict__ outW,
                       const float* __restrict__ bo,
                       const float* __restrict__ outb) {
    int idx = blockIdx.x*blockDim.x + threadIdx.x;
    const int N_ADJ = VV*VV*LL;
    const int N_E   = KAB*HH;
    const int N_WF  = VV*HH;
    if (idx < N_ADJ) {
        g_adj[idx] = 1.0f/(1.0f + __expf(-adjl[idx]));
    } else if (idx < N_ADJ + N_E) {
        int t = idx - N_ADJ;
        int j = t / HH, h = t % HH;
        float val = 0.0f;
        if (j < VV)          val = var_emb[j*HH + h];
        else if (j < VV+LL)  val = temp_emb[(j-VV)*HH + h];
        g_E[j*HH + h] = val;
    } else if (idx < N_ADJ + N_E + N_WF) {
        int t = idx - N_ADJ - N_E;
        int v = t / HH, h = t % HH;
        const float* wrow = Wo + (v*HH + h)*HH;
        const float* ow   = outW + v*HH;
        float acc = 0.0f;
        for (int k = 0; k < HH; k++) acc = fmaf(wrow[k], ow[k], acc);
        g_wf[v*HH + h] = acc;
    } else if (idx < N_ADJ + N_E + N_WF + VV) {
        int v = idx - N_ADJ - N_E - N_WF;
        float acc = outb[v];
        for (int k = 0; k < HH; k++) acc = fmaf(bo[v*HH+k], outW[v*HH+k], acc);
        g_bf[v] = acc;
    }
}

// ---------------- transpose + tf32-round the 6 weight sets: g_Wt[n][k] = W[k][n] ----------------
__global__ void __launch_bounds__(256) k_transpose(const float* __restrict__ mechW,
        const float* __restrict__ Wq, const float* __restrict__ Wk, const float* __restrict__ Wv) {
    extern __shared__ float sm[];     // 128 x 129 floats
    int mat = blockIdx.x >> 6;        // 0..5
    int v   = blockIdx.x & 63;
    const float* src;
    if (mat < 3)       src = mechW + ((size_t)v*NLL + mat)*HH*HH;
    else if (mat == 3) src = Wq + (size_t)v*HH*HH;
    else if (mat == 4) src = Wk + (size_t)v*HH*HH;
    else               src = Wv + (size_t)v*HH*HH;
    float* dst = g_Wt + ((size_t)mat*VV + v)*HH*HH;
    int tid = threadIdx.x;
    for (int idx = tid; idx < HH*HH/4; idx += 256) {
        int k = idx >> 5, c4 = idx & 31;
        float4 w = ((const float4*)src)[idx];
        float* p = sm + k*129 + 4*c4;
        p[0]=w.x; p[1]=w.y; p[2]=w.z; p[3]=w.w;
    }
    __syncthreads();
    for (int idx = tid; idx < HH*HH/4; idx += 256) {
        int n = idx >> 5, k4 = idx & 31;
        int k = 4*k4;
        uint4 u;
        u.x = f2tf32(sm[(k+0)*129 + n]);
        u.y = f2tf32(sm[(k+1)*129 + n]);
        u.z = f2tf32(sm[(k+2)*129 + n]);
        u.w = f2tf32(sm[(k+3)*129 + n]);
        ((uint4*)(dst + n*HH))[k4] = u;
    }
}

// ---------------- lag-mix (unchanged, proven) ----------------
__global__ void k_lagmix(const float* __restrict__ x) {
    extern __shared__ float sm[];
    float* x_sm   = sm;
    float* adj_sm = sm + SS*VV;
    int i = blockIdx.x & (VV-1);
    int b = blockIdx.x >> 6;
    int tid = threadIdx.x;

    const float4* xg = (const float4*)(x + b*SS*VV);
    float4* xs4 = (float4*)x_sm;
    for (int p = tid; p < SS*VV/4; p += 256) xs4[p] = xg[p];
    for (int p = tid; p < VV*LL; p += 256) {
        int s = p / LL, l = p % LL;
        adj_sm[p] = g_adj[(s*VV + i)*LL + l];
    }
    __syncthreads();
    {
        int s  = tid & 63;
        int tg = tid >> 6;
        float a[LL];
        #pragma unroll
        for (int l = 0; l < LL; l++) a[l] = adj_sm[s*LL + l];
        for (int t = tg; t < SS; t += 4) {
            float acc = 0.0f;
            #pragma unroll
            for (int l = 0; l < LL; l++)
                if (t >= l) acc = fmaf(x_sm[(t-l)*VV + s], a[l], acc);
            g_AB[((b*SS + t)*VV + i)*KAB + s] = acc;
        }
    }
    {
        int w = tid >> 5, lane = tid & 31;
        for (int tt = 0; tt < 32; tt++) {
            int t = w*32 + tt;
            int rowbase = ((b*SS + t)*VV + i)*KAB;
            #pragma unroll
            for (int l = 0; l < LL; l++) {
                float p = 0.0f;
                if (t >= l) {
                    const float* xr = x_sm + (t-l)*VV;
                    p = xr[lane]      * adj_sm[lane*LL + l]
                      + xr[lane + 32] * adj_sm[(lane+32)*LL + l];
                }
                #pragma unroll
                for (int off = 16; off; off >>= 1) p += __shfl_xor_sync(0xffffffffu, p, off);
                if (lane == 0) g_AB[rowbase + VV + l] = p;
            }
            if (lane < (KAB - VV - LL)) g_AB[rowbase + VV + LL + lane] = 0.0f;
        }
    }
}

// ---------------- fp32 warp GEMM (embed only, proven) ----------------
template<int K>
__device__ __forceinline__ void warp_gemm4(const float* stg, const float4* W4, int lane,
                                           float4& a0, float4& a1, float4& a2, float4& a3) {
    const float4* s0 = (const float4*)(stg);
    const float4* s1 = (const float4*)(stg + K);
    const float4* s2 = (const float4*)(stg + 2*K);
    const float4* s3 = (const float4*)(stg + 3*K);
    #pragma unroll 4
    for (int k4 = 0; k4 < K/4; k4++) {
        float4 z0 = s0[k4], z1 = s1[k4], z2 = s2[k4], z3 = s3[k4];
        #pragma unroll
        for (int kk = 0; kk < 4; kk++) {
            float4 wv = W4[(k4*4 + kk)*32 + lane];
            float f0 = (kk==0)?z0.x:(kk==1)?z0.y:(kk==2)?z0.z:z0.w;
            float f1 = (kk==0)?z1.x:(kk==1)?z1.y:(kk==2)?z1.z:z1.w;
            float f2 = (kk==0)?z2.x:(kk==1)?z2.y:(kk==2)?z2.z:z2.w;
            float f3 = (kk==0)?z3.x:(kk==1)?z3.y:(kk==2)?z3.z:z3.w;
            a0.x = fmaf(f0, wv.x, a0.x); a0.y = fmaf(f0, wv.y, a0.y);
            a0.z = fmaf(f0, wv.z, a0.z); a0.w = fmaf(f0, wv.w, a0.w);
            a1.x = fmaf(f1, wv.x, a1.x); a1.y = fmaf(f1, wv.y, a1.y);
            a1.z = fmaf(f1, wv.z, a1.z); a1.w = fmaf(f1, wv.w, a1.w);
            a2.x = fmaf(f2, wv.x, a2.x); a2.y = fmaf(f2, wv.y, a2.y);
            a2.z = fmaf(f2, wv.z, a2.z); a2.w = fmaf(f2, wv.w, a2.w);
            a3.x = fmaf(f3, wv.x, a3.x); a3.y = fmaf(f3, wv.y, a3.y);
            a3.z = fmaf(f3, wv.z, a3.z); a3.w = fmaf(f3, wv.w, a3.w);
        }
    }
}

// ---------------- embedding GEMM: z = AB(65536x80) @ E(80x128) ----------------
__global__ void __launch_bounds__(256) k_embed() {
    extern __shared__ float sm[];
    float* Esm = sm;
    float* stg = sm + KAB*HH;
    int tid = threadIdx.x, w = tid >> 5, lane = tid & 31;
    float4* E4 = (float4*)Esm;
    for (int p = tid; p < KAB*HH/4; p += 256) E4[p] = ((const float4*)g_E)[p];
    __syncthreads();
    int r0 = blockIdx.x*128 + w*16;
    float* mystg = stg + w*4*KAB;
    const float4 zero4 = make_float4(0,0,0,0);
    for (int m = 0; m < 4; m++) {
        int rb = r0 + m*4;
        __syncwarp();
        #pragma unroll
        for (int rr = 0; rr < 4; rr++)
            if (lane < KAB/4)
                ((float4*)(mystg + rr*KAB))[lane] = ((const float4*)(g_AB + (rb+rr)*KAB))[lane];
        __syncwarp();
        float4 a0 = zero4, a1 = zero4, a2 = zero4, a3 = zero4;
        warp_gemm4<KAB>(mystg, E4, lane, a0, a1, a2, a3);
        ((float4*)(g_z + (rb+0)*HH))[lane] = a0;
        ((float4*)(g_z + (rb+1)*HH))[lane] = a1;
        ((float4*)(g_z + (rb+2)*HH))[lane] = a2;
        ((float4*)(g_z + (rb+3)*HH))[lane] = a3;
    }
}

// ---------------- fused mech x3 + QKV chain via mma.sync tf32 (proven R8) ----------------
__global__ void __launch_bounds__(256, 1) k_chain(const float* __restrict__ mech_b,
        const float* __restrict__ ln_g, const float* __restrict__ ln_b,
        const float* __restrict__ bqv, const float* __restrict__ bkv,
        const float* __restrict__ bvv) {
    extern __shared__ float smf[];
    float* Wsm = smf;                         // 128 x PW floats (also C' staging)
    float* Zsm = smf + HH*PW;                 // 128 x PZ floats
    float* bias_sm = smf + HH*PW + HH*PZ;     // 128
    float* g_sm    = bias_sm + HH;            // 128
    float* be_sm   = g_sm + HH;               // 128
    uint32_t* Wu = (uint32_t*)Wsm;
    uint32_t* Zu = (uint32_t*)Zsm;

    int tid  = threadIdx.x;
    int w    = tid >> 5, lane = tid & 31;
    int gid  = lane >> 2, qid = lane & 3;
    int v    = blockIdx.y;
    int r0   = blockIdx.x * 128;
    int n0   = (w & 1) * 64;
    int m0   = (w >> 1) * 32;

    for (int it = 0; it < 16; it++) {
        int m = w + 8*it;
        float4 zv = ((const float4*)(g_z + ((size_t)(r0+m)*VV + v)*HH))[lane];
        uint4 u; u.x=f2tf32(zv.x); u.y=f2tf32(zv.y); u.z=f2tf32(zv.z); u.w=f2tf32(zv.w);
        ((uint4*)(Zu + m*PZ))[lane] = u;
    }

    #pragma unroll 1
    for (int phase = 0; phase < 6; phase++) {
        __syncthreads();
        {
            const float4* src = (const float4*)(g_Wt + ((size_t)phase*VV + v)*HH*HH);
            #pragma unroll
            for (int i = 0; i < 16; i++) {
                int idx = tid + 256*i;
                int n = idx >> 5, k4 = idx & 31;
                ((float4*)(Wsm + n*PW))[k4] = src[idx];
            }
        }
        if (tid < HH) {
            if (phase < 3) {
                bias_sm[tid] = mech_b[((size_t)v*NLL + phase)*HH + tid];
                g_sm[tid]    = ln_g  [((size_t)v*NLL + phase)*HH + tid];
                be_sm[tid]   = ln_b  [((size_t)v*NLL + phase)*HH + tid];
            } else {
                const float* bp = (phase == 3) ? bqv : (phase == 4) ? bkv : bvv;
                bias_sm[tid] = bp[v*HH + tid];
            }
        }
        __syncthreads();

        float acc[4][4][4];
        #pragma unroll
        for (int nt = 0; nt < 4; nt++)
            #pragma unroll
            for (int mt = 0; mt < 4; mt++)
                #pragma unroll
                for (int r = 0; r < 4; r++) acc[nt][mt][r] = 0.0f;

        #pragma unroll 4
        for (int s = 0; s < 16; s++) {
            int k0 = 8*s;
            uint32_t Af[4][4], Bf[4][2];
            #pragma unroll
            for (int nt = 0; nt < 4; nt++) {
                const uint32_t* p = Wu + (n0 + nt*16 + gid)*PW + k0 + qid;
                Af[nt][0] = p[0];
                Af[nt][1] = p[8*PW];
                Af[nt][2] = p[4];
                Af[nt][3] = p[8*PW + 4];
            }
            #pragma unroll
            for (int mt = 0; mt < 4; mt++) {
                const uint32_t* q = Zu + (m0 + mt*8 + gid)*PZ + k0 + qid;
                Bf[mt][0] = q[0];
                Bf[mt][1] = q[4];
            }
            #pragma unroll
            for (int nt = 0; nt < 4; nt++)
                #pragma unroll
                for (int mt = 0; mt < 4; mt++)
                    mma_tf32(acc[nt][mt], Af[nt], Bf[mt]);
        }
        __syncthreads();

        #pragma unroll
        for (int nt = 0; nt < 4; nt++) {
            int nb = n0 + nt*16 + gid;
            #pragma unroll
            for (int mt = 0; mt < 4; mt++) {
                int mb = m0 + mt*8 + 2*qid;
                Wsm[ mb   *PW + nb    ] = acc[nt][mt][0];
                Wsm[(mb+1)*PW + nb    ] = acc[nt][mt][1];
                Wsm[ mb   *PW + nb + 8] = acc[nt][mt][2];
                Wsm[(mb+1)*PW + nb + 8] = acc[nt][mt][3];
            }
        }
        __syncthreads();

        if (phase < 3) {
            for (int it = 0; it < 16; it++) {
                int m = w + 8*it;
                float4 c = ((const float4*)(Wsm + m*PW))[lane];
                float4 b4 = ((const float4*)bias_sm)[lane];
                c.x += b4.x; c.y += b4.y; c.z += b4.z; c.w += b4.w;
                float s  = c.x + c.y + c.z + c.w;
                float ss = c.x*c.x + c.y*c.y + c.z*c.z + c.w*c.w;
                #pragma unroll
                for (int off = 16; off; off >>= 1) {
                    s  += __shfl_xor_sync(0xffffffffu, s,  off);
                    ss += __shfl_xor_sync(0xffffffffu, ss, off);
                }
                float mu   = s * (1.0f/128.0f);
                float var  = ss * (1.0f/128.0f) - mu*mu;
                float rstd = rsqrtf(var + 1e-5f);
                float4 g4  = ((const float4*)g_sm)[lane];
                float4 be4 = ((const float4*)be_sm)[lane];
                const float ic = 0.70710678118654752440f;
                float y;
                uint4 u;
                y = (c.x - mu)*rstd*g4.x + be4.x; y = 0.5f*y*(1.0f + erff(y*ic)); u.x = f2tf32(y);
                y = (c.y - mu)*rstd*g4.y + be4.y; y = 0.5f*y*(1.0f + erff(y*ic)); u.y = f2tf32(y);
                y = (c.z - mu)*rstd*g4.z + be4.z; y = 0.5f*y*(1.0f + erff(y*ic)); u.z = f2tf32(y);
                y = (c.w - mu)*rstd*g4.w + be4.w; y = 0.5f*y*(1.0f + erff(y*ic)); u.w = f2tf32(y);
                ((uint4*)(Zu + m*PZ))[lane] = u;
            }
        } else {
            float* outp = (phase == 3) ? g_q : (phase == 4) ? g_k : g_v;
            for (int it = 0; it < 16; it++) {
                int m = w + 8*it;
                float4 c = ((const float4*)(Wsm + m*PW))[lane];
                float4 b4 = ((const float4*)bias_sm)[lane];
                c.x += b4.x; c.y += b4.y; c.z += b4.z; c.w += b4.w;
                ((float4*)(outp + ((size_t)(r0+m)*VV + v)*HH))[lane] = c;
            }
        }
    }
}

// ---------------- attention via mma.sync tf32 ----------------
__global__ void __launch_bounds__(256, 1) k_attn2() {
    __shared__ uint32_t Ks[SS*PK];   // 20KB, tf32 bits
    __shared__ uint32_t Vs[SS*PVT];  // 24KB, tf32 bits
    int bid  = blockIdx.x;
    int half = bid & 1;
    int v    = (bid >> 1) & (VV-1);
    int b    = bid >> 7;
    int tid  = threadIdx.x;
    int w    = tid >> 5, lane = tid & 31;
    int gid  = lane >> 2, qid = lane & 3;
    const size_t RSTR = (size_t)VV*HH;
    const size_t rowbase = ((size_t)(b*SS)*VV + v)*HH;

    #pragma unroll 1
    for (int hh = 0; hh < 4; hh++) {
        int hbase = (half*4 + hh)*DHH;
        __syncthreads();   // protect prior head's Ks/Vs reads
        {
            const float* kp = g_k + rowbase + (size_t)tid*RSTR + hbase;
            const float* vp = g_v + rowbase + (size_t)tid*RSTR + hbase;
            #pragma unroll
            for (int c4 = 0; c4 < 4; c4++) {
                float4 kv = ((const float4*)kp)[c4];
                float4 vv = ((const float4*)vp)[c4];
                uint32_t* kd = Ks + tid*PK + 4*c4;
                uint32_t* vd = Vs + tid*PVT + 4*c4;
                kd[0] = f2tf32(kv.x); kd[1] = f2tf32(kv.y);
                kd[2] = f2tf32(kv.z); kd[3] = f2tf32(kv.w);
                vd[0] = f2tf32(vv.x); vd[1] = f2tf32(vv.y);
                vd[2] = f2tf32(vv.z); vd[3] = f2tf32(vv.w);
            }
        }
        __syncthreads();

        #pragma unroll 1
        for (int rep = 0; rep < 2; rep++) {
            int q0 = (w + 8*rep) * 16;
            uint32_t Aq[2][4];
            const float* qp = g_q + rowbase + (size_t)q0*RSTR + hbase;
            #pragma unroll
            for (int ks = 0; ks < 2; ks++) {
                int k0 = 8*ks;
                Aq[ks][0] = f2tf32(0.25f*qp[(size_t) gid   *RSTR + k0 + qid    ]);
                Aq[ks][1] = f2tf32(0.25f*qp[(size_t)(gid+8)*RSTR + k0 + qid    ]);
                Aq[ks][2] = f2tf32(0.25f*qp[(size_t) gid   *RSTR + k0 + qid + 4]);
                Aq[ks][3] = f2tf32(0.25f*qp[(size_t)(gid+8)*RSTR + k0 + qid + 4]);
            }
            float sacc[32][4];
            #pragma unroll
            for (int nt = 0; nt < 32; nt++)
                { sacc[nt][0]=0.f; sacc[nt][1]=0.f; sacc[nt][2]=0.f; sacc[nt][3]=0.f; }
            #pragma unroll
            for (int nt = 0; nt < 32; nt++) {
                #pragma unroll
                for (int ks = 0; ks < 2; ks++) {
                    uint32_t Bf[2];
                    const uint32_t* kp2 = Ks + (nt*8 + gid)*PK + 8*ks + qid;
                    Bf[0] = kp2[0];
                    Bf[1] = kp2[4];
                    mma_tf32(sacc[nt], Aq[ks], Bf);
                }
            }
            float m0 = -1e30f, m1 = -1e30f;
            #pragma unroll
            for (int nt = 0; nt < 32; nt++) {
                m0 = fmaxf(m0, fmaxf(sacc[nt][0], sacc[nt][1]));
                m1 = fmaxf(m1, fmaxf(sacc[nt][2], sacc[nt][3]));
            }
            m0 = fmaxf(m0, __shfl_xor_sync(0xffffffffu, m0, 1));
            m0 = fmaxf(m0, __shfl_xor_sync(0xffffffffu, m0, 2));
            m1 = fmaxf(m1, __shfl_xor_sync(0xffffffffu, m1, 1));
            m1 = fmaxf(m1, __shfl_xor_sync(0xffffffffu, m1, 2));
            float s0 = 0.f, s1 = 0.f;
            uint32_t* su = (uint32_t*)sacc;
            #pragma unroll
            for (int nt = 0; nt < 32; nt++) {
                float e0 = __expf(sacc[nt][0] - m0);
                float e1 = __expf(sacc[nt][1] - m0);
                float e2 = __expf(sacc[nt][2] - m1);
                float e3 = __expf(sacc[nt][3] - m1);
                s0 += e0 + e1; s1 += e2 + e3;
                su[4*nt+0] = f2tf32(e0); su[4*nt+1] = f2tf32(e1);
                su[4*nt+2] = f2tf32(e2); su[4*nt+3] = f2tf32(e3);
            }
            s0 += __shfl_xor_sync(0xffffffffu, s0, 1);
            s0 += __shfl_xor_sync(0xffffffffu, s0, 2);
            s1 += __shfl_xor_sync(0xffffffffu, s1, 1);
            s1 += __shfl_xor_sync(0xffffffffu, s1, 2);
            float inv0 = 1.0f/s0, inv1 = 1.0f/s1;
            float oacc[2][4];
            oacc[0][0]=0.f; oacc[0][1]=0.f; oacc[0][2]=0.f; oacc[0][3]=0.f;
            oacc[1][0]=0.f; oacc[1][1]=0.f; oacc[1][2]=0.f; oacc[1][3]=0.f;
            int src_lo = (lane & ~3) | (qid >> 1);
            int src_hi = src_lo + 2;
            int psel   = qid & 1;
            #pragma unroll
            for (int kc = 0; kc < 32; kc++) {
                uint32_t aP[4];
                uint32_t e0 = __shfl_sync(0xffffffffu, su[4*kc+0], src_lo);
                uint32_t e1 = __shfl_sync(0xffffffffu, su[4*kc+1], src_lo);
                aP[0] = psel ? e1 : e0;
                uint32_t g0 = __shfl_sync(0xffffffffu, su[4*kc+2], src_lo);
                uint32_t g1 = __shfl_sync(0xffffffffu, su[4*kc+3], src_lo);
                aP[1] = psel ? g1 : g0;
                uint32_t h0 = __shfl_sync(0xffffffffu, su[4*kc+0], src_hi);
                uint32_t h1 = __shfl_sync(0xffffffffu, su[4*kc+1], src_hi);
                aP[2] = psel ? h1 : h0;
                uint32_t i0 = __shfl_sync(0xffffffffu, su[4*kc+2], src_hi);
                uint32_t i1 = __shfl_sync(0xffffffffu, su[4*kc+3], src_hi);
                aP[3] = psel ? i1 : i0;
                #pragma unroll
                for (int nt2 = 0; nt2 < 2; nt2++) {
                    uint32_t Bv[2];
                    const uint32_t* vp2 = Vs + (kc*8 + qid)*PVT + nt2*8 + gid;
                    Bv[0] = vp2[0];
                    Bv[1] = vp2[4*PVT];
                    mma_tf32(oacc[nt2], aP, Bv);
                }
            }
            #pragma unroll
            for (int nt2 = 0; nt2 < 2; nt2++) {
                float* olo = g_o + rowbase + (size_t)(q0+gid  )*RSTR + hbase + nt2*8 + 2*qid;
                float* ohi = g_o + rowbase + (size_t)(q0+gid+8)*RSTR + hbase + nt2*8 + 2*qid;
                ((float2*)olo)[0] = make_float2(oacc[nt2][0]*inv0, oacc[nt2][1]*inv0);
                ((float2*)ohi)[0] = make_float2(oacc[nt2][2]*inv1, oacc[nt2][3]*inv1);
            }
        }
    }
}

// ---------------- output head ----------------
__global__ void k_out(float* __restrict__ out) {
    int w = threadIdx.x >> 5, lane = threadIdx.x & 31;
    int r = blockIdx.x*8 + w;
    int v = r & (VV-1);
    float4 o4 = ((const float4*)(g_o  + r*HH))[lane];
    float4 w4 = ((const float4*)(g_wf + v*HH))[lane];
    float p = o4.x*w4.x + o4.y*w4.y + o4.z*w4.z + o4.w*w4.w;
    #pragma unroll
    for (int off = 16; off; off >>= 1) p += __shfl_xor_sync(0xffffffffu, p, off);
    if (lane == 0) out[r] = p + g_bf[v];
}

// ---------------- launch ----------------
extern "C" void kernel_launch(void* const* d_in, const int* in_sizes, int n_in,
                              void* d_out, int out_size) {
    (void)in_sizes; (void)n_in; (void)out_size;
    const float* x        = (const float*)d_in[0];
    const float* adjl     = (const float*)d_in[1];
    const float* var_emb  = (const float*)d_in[2];
    const float* temp_emb = (const float*)d_in[3];
    const float* mech_W   = (const float*)d_in[4];
    const float* mech_b   = (const float*)d_in[5];
    const float* ln_g     = (const float*)d_in[6];
    const float* ln_b     = (const float*)d_in[7];
    const float* Wq       = (const float*)d_in[8];
    const float* Wk       = (const float*)d_in[9];
    const float* Wv       = (const float*)d_in[10];
    const float* Wo       = (const float*)d_in[11];
    const float* bq       = (const float*)d_in[12];
    const float* bk       = (const float*)d_in[13];
    const float* bv       = (const float*)d_in[14];
    const float* bo       = (const float*)d_in[15];
    const float* outW     = (const float*)d_in[16];
    const float* outb     = (const float*)d_in[17];
    float* out = (float*)d_out;

    const int SMEM_LAG   = (SS*VV + VV*LL)*4;
    const int SMEM_EMB   = (KAB*HH + 8*4*KAB)*4;
    const int SMEM_TRANS = HH*129*4;
    const int SMEM_CHAIN = (HH*PW + HH*PZ + 3*HH)*4;
    cudaFuncSetAttribute(k_lagmix,    cudaFuncAttributeMaxDynamicSharedMemorySize, SMEM_LAG);
    cudaFuncSetAttribute(k_embed,     cudaFuncAttributeMaxDynamicSharedMemorySize, SMEM_EMB);
    cudaFuncSetAttribute(k_transpose, cudaFuncAttributeMaxDynamicSharedMemorySize, SMEM_TRANS);
    cudaFuncSetAttribute(k_chain,     cudaFuncAttributeMaxDynamicSharedMemorySize, SMEM_CHAIN);

    k_prep<<<(63552 + 255)/256, 256>>>(adjl, var_emb, temp_emb, Wo, outW, bo, outb);
    k_transpose<<<6*VV, 256, SMEM_TRANS>>>(mech_W, Wq, Wk, Wv);
    k_lagmix<<<BB*VV, 256, SMEM_LAG>>>(x);
    k_embed<<<NROWS/128, 256, SMEM_EMB>>>();

    dim3 gchain(BS/128, VV);   // (8, 64)
    k_chain<<<gchain, 256, SMEM_CHAIN>>>(mech_b, ln_g, ln_b, bq, bk, bv);

    k_attn2<<<BB*VV*2, 256>>>();
    k_out<<<NROWS/8, 256>>>(out);
}

// round 14
// speedup vs baseline: 2.1625x; 1.0746x over previous
#include <cuda_runtime.h>
#include <math.h>
#include <stdint.h>

#define BB 4
#define SS 256
#define VV 64
#define LL 11            // L+1
#define HH 128
#define NHH 8
#define DHH 16
#define NLL 3
#define BS (BB*SS)       // 1024
#define NROWS (BB*SS*VV) // 65536
#define KAB 80           // 64 (A) + 11 (Bl) + 5 pad

// smem pitches (floats) chosen for conflict-free mma fragment access
#define PW 136           // Wsm: bank = 8n + k  -> distinct over (n:8, k:4)
#define PZ 132           // Zsm: bank = 4m + k  -> distinct over (m:8, k:4)
#define PK 20            // attn K: bank = 20*gid + qid -> all 32 distinct
#define PVT 24           // attn V: bank = 24*qid + gid -> all 32 distinct

// ---------------- device scratch ----------------
__device__ float g_adj[VV*VV*LL];
__device__ float g_Et[HH*KAB];    // E^T[n][k], tf32 bits
__device__ float g_wf[VV*HH];
__device__ float g_bf[VV];
__device__ float g_AB[NROWS*KAB];
__device__ float g_q [NROWS*HH];
__device__ float g_k [NROWS*HH];
__device__ float g_v [NROWS*HH];
// transposed (W^T[n][k]) + tf32-rounded weights: [6 mats][64 v][128*128]
__device__ float g_Wt[6*VV*HH*HH];

// ---------------- helpers ----------------
__device__ __forceinline__ uint32_t f2tf32(float x) {
    uint32_t r; asm("cvt.rna.tf32.f32 %0, %1;" : "=r"(r) : "f"(x)); return r;
}
__device__ __forceinline__ void mma_tf32(float* c, const uint32_t* a, const uint32_t* b) {
    asm volatile(
        "mma.sync.aligned.m16n8k8.row.col.f32.tf32.tf32.f32 "
        "{%0,%1,%2,%3}, {%4,%5,%6,%7}, {%8,%9}, {%0,%1,%2,%3};"
        : "+f"(c[0]), "+f"(c[1]), "+f"(c[2]), "+f"(c[3])
        : "r"(a[0]), "r"(a[1]), "r"(a[2]), "r"(a[3]), "r"(b[0]), "r"(b[1]));
}

// ---------------- prep: sigmoid(adj), E^T (tf32), bf ----------------
__global__ void k_prep(const float* __restrict__ adjl,
                       const float* __restrict__ var_emb,
                       const float* __restrict__ temp_emb,
                       const float* __restrict__ outW,
                       const float* __restrict__ bo,
                       const float* __restrict__ outb) {
    int idx = blockIdx.x*blockDim.x + threadIdx.x;
    const int N_ADJ = VV*VV*LL;      // 45056
    const int N_ET  = HH*KAB;        // 10240
    if (idx < N_ADJ) {
        g_adj[idx] = 1.0f/(1.0f + __expf(-adjl[idx]));
    } else if (idx < N_ADJ + N_ET) {
        int t = idx - N_ADJ;
        int n = t / KAB, k = t % KAB;
        float val = 0.0f;
        if (k < VV)          val = var_emb[k*HH + n];
        else if (k < VV+LL)  val = temp_emb[(k-VV)*HH + n];
        g_Et[n*KAB + k] = __uint_as_float(f2tf32(val));
    } else if (idx < N_ADJ + N_ET + VV) {
        int v = idx - N_ADJ - N_ET;
        float acc = outb[v];
        for (int k = 0; k < HH; k++) acc = fmaf(bo[v*HH+k], outW[v*HH+k], acc);
        g_bf[v] = acc;
    }
}

// ---------------- prep: wf[v][h] = Wo[v][h][:] . outW[v][:], warp per output ----------------
__global__ void __launch_bounds__(256) k_prepwf(const float* __restrict__ Wo,
                                                const float* __restrict__ outW) {
    int w = threadIdx.x >> 5, lane = threadIdx.x & 31;
    int r = blockIdx.x*8 + w;          // r = v*128 + h, 8192 total
    int v = r >> 7;
    float4 a = ((const float4*)(Wo + (size_t)r*HH))[lane];
    float4 b = ((const float4*)(outW + v*HH))[lane];
    float p = a.x*b.x + a.y*b.y + a.z*b.z + a.w*b.w;
    #pragma unroll
    for (int off = 16; off; off >>= 1) p += __shfl_xor_sync(0xffffffffu, p, off);
    if (lane == 0) g_wf[r] = p;
}

// ---------------- init out with bf ----------------
__global__ void k_initout(float* __restrict__ out) {
    int idx = blockIdx.x*blockDim.x + threadIdx.x;
    out[idx] = g_bf[idx & (VV-1)];
}

// ---------------- transpose + tf32-round the 6 weight sets: g_Wt[n][k] = W[k][n] ----------------
__global__ void __launch_bounds__(256) k_transpose(const float* __restrict__ mechW,
        const float* __restrict__ Wq, const float* __restrict__ Wk, const float* __restrict__ Wv) {
    extern __shared__ float sm[];     // 128 x 129 floats
    int mat = blockIdx.x >> 6;        // 0..5
    int v   = blockIdx.x & 63;
    const float* src;
    if (mat < 3)       src = mechW + ((size_t)v*NLL + mat)*HH*HH;
    else if (mat == 3) src = Wq + (size_t)v*HH*HH;
    else if (mat == 4) src = Wk + (size_t)v*HH*HH;
    else               src = Wv + (size_t)v*HH*HH;
    float* dst = g_Wt + ((size_t)mat*VV + v)*HH*HH;
    int tid = threadIdx.x;
    for (int idx = tid; idx < HH*HH/4; idx += 256) {
        int k = idx >> 5, c4 = idx & 31;
        float4 w = ((const float4*)src)[idx];
        float* p = sm + k*129 + 4*c4;
        p[0]=w.x; p[1]=w.y; p[2]=w.z; p[3]=w.w;
    }
    __syncthreads();
    for (int idx = tid; idx < HH*HH/4; idx += 256) {
        int n = idx >> 5, k4 = idx & 31;
        int k = 4*k4;
        uint4 u;
        u.x = f2tf32(sm[(k+0)*129 + n]);
        u.y = f2tf32(sm[(k+1)*129 + n]);
        u.z = f2tf32(sm[(k+2)*129 + n]);
        u.w = f2tf32(sm[(k+3)*129 + n]);
        ((uint4*)(dst + n*HH))[k4] = u;
    }
}

// ---------------- lag-mix (unchanged, proven) ----------------
__global__ void k_lagmix(const float* __restrict__ x) {
    extern __shared__ float sm[];
    float* x_sm   = sm;
    float* adj_sm = sm + SS*VV;
    int i = blockIdx.x & (VV-1);
    int b = blockIdx.x >> 6;
    int tid = threadIdx.x;

    const float4* xg = (const float4*)(x + b*SS*VV);
    float4* xs4 = (float4*)x_sm;
    for (int p = tid; p < SS*VV/4; p += 256) xs4[p] = xg[p];
    for (int p = tid; p < VV*LL; p += 256) {
        int s = p / LL, l = p % LL;
        adj_sm[p] = g_adj[(s*VV + i)*LL + l];
    }
    __syncthreads();
    {
        int s  = tid & 63;
        int tg = tid >> 6;
        float a[LL];
        #pragma unroll
        for (int l = 0; l < LL; l++) a[l] = adj_sm[s*LL + l];
        for (int t = tg; t < SS; t += 4) {
            float acc = 0.0f;
            #pragma unroll
            for (int l = 0; l < LL; l++)
                if (t >= l) acc = fmaf(x_sm[(t-l)*VV + s], a[l], acc);
            g_AB[((b*SS + t)*VV + i)*KAB + s] = acc;
        }
    }
    {
        int w = tid >> 5, lane = tid & 31;
        for (int tt = 0; tt < 32; tt++) {
            int t = w*32 + tt;
            int rowbase = ((b*SS + t)*VV + i)*KAB;
            #pragma unroll
            for (int l = 0; l < LL; l++) {
                float p = 0.0f;
                if (t >= l) {
                    const float* xr = x_sm + (t-l)*VV;
                    p = xr[lane]      * adj_sm[lane*LL + l]
                      + xr[lane + 32] * adj_sm[(lane+32)*LL + l];
                }
                #pragma unroll
                for (int off = 16; off; off >>= 1) p += __shfl_xor_sync(0xffffffffu, p, off);
                if (lane == 0) g_AB[rowbase + VV + l] = p;
            }
            if (lane < (KAB - VV - LL)) g_AB[rowbase + VV + LL + lane] = 0.0f;
        }
    }
}

// ---------------- fused embed + mech x3 + QKV chain via mma.sync tf32 ----------------
// CTA = (row-tile of 128, variable v); 256 threads (8 warps).
// phase -1: z = AB @ E  (A-operand = E^T in Wsm, B-operand = AB in Zsm, K=80)
// phases 0..5: out^T[n][m] = W^T[n][k] * z[m][k], LN+GELU / bias epilogues.
__global__ void __launch_bounds__(256, 1) k_chain(const float* __restrict__ mech_b,
        const float* __restrict__ ln_g, const float* __restrict__ ln_b,
        const float* __restrict__ bqv, const float* __restrict__ bkv,
        const float* __restrict__ bvv) {
    extern __shared__ float smf[];
    float* Wsm = smf;                         // 128 x PW floats (also C' staging)
    float* Zsm = smf + HH*PW;                 // 128 x PZ floats
    float* bias_sm = smf + HH*PW + HH*PZ;     // 128
    float* g_sm    = bias_sm + HH;            // 128
    float* be_sm   = g_sm + HH;               // 128
    uint32_t* Wu = (uint32_t*)Wsm;
    uint32_t* Zu = (uint32_t*)Zsm;

    int tid  = threadIdx.x;
    int w    = tid >> 5, lane = tid & 31;
    int gid  = lane >> 2, qid = lane & 3;
    int v    = blockIdx.y;
    int r0   = blockIdx.x * 128;
    int n0   = (w & 1) * 64;
    int m0   = (w >> 1) * 32;

    // ======== phase -1: embed z = AB @ E ========
    // load E^T (128 x 80 tf32 bits) into Wsm
    #pragma unroll
    for (int i = 0; i < 10; i++) {
        int idx = tid + 256*i;        // 2560 float4 = 128 rows x 20
        int n = idx / 20, k4 = idx % 20;
        ((float4*)(Wsm + n*PW))[k4] = ((const float4*)g_Et)[idx];
    }
    // load AB rows (tf32-rounded) into Zsm
    for (int it = 0; it < 16; it++) {
        int m = w + 8*it;
        if (lane < 20) {
            float4 ab = ((const float4*)(g_AB + ((size_t)(r0+m)*VV + v)*KAB))[lane];
            uint4 u; u.x=f2tf32(ab.x); u.y=f2tf32(ab.y); u.z=f2tf32(ab.z); u.w=f2tf32(ab.w);
            ((uint4*)(Zu + m*PZ))[lane] = u;
        }
    }
    __syncthreads();
    {
        float acc[4][4][4];
        #pragma unroll
        for (int nt = 0; nt < 4; nt++)
            #pragma unroll
            for (int mt = 0; mt < 4; mt++)
                #pragma unroll
                for (int r = 0; r < 4; r++) acc[nt][mt][r] = 0.0f;
        #pragma unroll 2
        for (int s = 0; s < 10; s++) {
            int k0 = 8*s;
            uint32_t Af[4][4], Bf[4][2];
            #pragma unroll
            for (int nt = 0; nt < 4; nt++) {
                const uint32_t* p = Wu + (n0 + nt*16 + gid)*PW + k0 + qid;
                Af[nt][0] = p[0];
                Af[nt][1] = p[8*PW];
                Af[nt][2] = p[4];
                Af[nt][3] = p[8*PW + 4];
            }
            #pragma unroll
            for (int mt = 0; mt < 4; mt++) {
                const uint32_t* q = Zu + (m0 + mt*8 + gid)*PZ + k0 + qid;
                Bf[mt][0] = q[0];
                Bf[mt][1] = q[4];
            }
            #pragma unroll
            for (int nt = 0; nt < 4; nt++)
                #pragma unroll
                for (int mt = 0; mt < 4; mt++)
                    mma_tf32(acc[nt][mt], Af[nt], Bf[mt]);
        }
        __syncthreads();   // done reading Wsm/Zsm -> stage C'
        #pragma unroll
        for (int nt = 0; nt < 4; nt++) {
            int nb = n0 + nt*16 + gid;
            #pragma unroll
            for (int mt = 0; mt < 4; mt++) {
                int mb = m0 + mt*8 + 2*qid;
                Wsm[ mb   *PW + nb    ] = acc[nt][mt][0];
                Wsm[(mb+1)*PW + nb    ] = acc[nt][mt][1];
                Wsm[ mb   *PW + nb + 8] = acc[nt][mt][2];
                Wsm[(mb+1)*PW + nb + 8] = acc[nt][mt][3];
            }
        }
        __syncthreads();
        // epilogue: z (tf32) into Zsm, no bias/LN
        for (int it = 0; it < 16; it++) {
            int m = w + 8*it;
            float4 c = ((const float4*)(Wsm + m*PW))[lane];
            uint4 u; u.x=f2tf32(c.x); u.y=f2tf32(c.y); u.z=f2tf32(c.z); u.w=f2tf32(c.w);
            ((uint4*)(Zu + m*PZ))[lane] = u;
        }
    }

    // ======== phases 0..5 ========
    #pragma unroll 1
    for (int phase = 0; phase < 6; phase++) {
        __syncthreads();
        {
            const float4* src = (const float4*)(g_Wt + ((size_t)phase*VV + v)*HH*HH);
            #pragma unroll
            for (int i = 0; i < 16; i++) {
                int idx = tid + 256*i;
                int n = idx >> 5, k4 = idx & 31;
                ((float4*)(Wsm + n*PW))[k4] = src[idx];
            }
        }
        if (tid < HH) {
            if (phase < 3) {
                bias_sm[tid] = mech_b[((size_t)v*NLL + phase)*HH + tid];
                g_sm[tid]    = ln_g  [((size_t)v*NLL + phase)*HH + tid];
                be_sm[tid]   = ln_b  [((size_t)v*NLL + phase)*HH + tid];
            } else {
                const float* bp = (phase == 3) ? bqv : (phase == 4) ? bkv : bvv;
                bias_sm[tid] = bp[v*HH + tid];
            }
        }
        __syncthreads();

        float acc[4][4][4];
        #pragma unroll
        for (int nt = 0; nt < 4; nt++)
            #pragma unroll
            for (int mt = 0; mt < 4; mt++)
                #pragma unroll
                for (int r = 0; r < 4; r++) acc[nt][mt][r] = 0.0f;

        #pragma unroll 4
        for (int s = 0; s < 16; s++) {
            int k0 = 8*s;
            uint32_t Af[4][4], Bf[4][2];
            #pragma unroll
            for (int nt = 0; nt < 4; nt++) {
                const uint32_t* p = Wu + (n0 + nt*16 + gid)*PW + k0 + qid;
                Af[nt][0] = p[0];
                Af[nt][1] = p[8*PW];
                Af[nt][2] = p[4];
                Af[nt][3] = p[8*PW + 4];
            }
            #pragma unroll
            for (int mt = 0; mt < 4; mt++) {
                const uint32_t* q = Zu + (m0 + mt*8 + gid)*PZ + k0 + qid;
                Bf[mt][0] = q[0];
                Bf[mt][1] = q[4];
            }
            #pragma unroll
            for (int nt = 0; nt < 4; nt++)
                #pragma unroll
                for (int mt = 0; mt < 4; mt++)
                    mma_tf32(acc[nt][mt], Af[nt], Bf[mt]);
        }
        __syncthreads();

        #pragma unroll
        for (int nt = 0; nt < 4; nt++) {
            int nb = n0 + nt*16 + gid;
            #pragma unroll
            for (int mt = 0; mt < 4; mt++) {
                int mb = m0 + mt*8 + 2*qid;
                Wsm[ mb   *PW + nb    ] = acc[nt][mt][0];
                Wsm[(mb+1)*PW + nb    ] = acc[nt][mt][1];
                Wsm[ mb   *PW + nb + 8] = acc[nt][mt][2];
                Wsm[(mb+1)*PW + nb + 8] = acc[nt][mt][3];
            }
        }
        __syncthreads();

        if (phase < 3) {
            for (int it = 0; it < 16; it++) {
                int m = w + 8*it;
                float4 c = ((const float4*)(Wsm + m*PW))[lane];
                float4 b4 = ((const float4*)bias_sm)[lane];
                c.x += b4.x; c.y += b4.y; c.z += b4.z; c.w += b4.w;
                float s  = c.x + c.y + c.z + c.w;
                float ss = c.x*c.x + c.y*c.y + c.z*c.z + c.w*c.w;
                #pragma unroll
                for (int off = 16; off; off >>= 1) {
                    s  += __shfl_xor_sync(0xffffffffu, s,  off);
                    ss += __shfl_xor_sync(0xffffffffu, ss, off);
                }
                float mu   = s * (1.0f/128.0f);
                float var  = ss * (1.0f/128.0f) - mu*mu;
                float rstd = rsqrtf(var + 1e-5f);
                float4 g4  = ((const float4*)g_sm)[lane];
                float4 be4 = ((const float4*)be_sm)[lane];
                const float ic = 0.70710678118654752440f;
                float y;
                uint4 u;
                y = (c.x - mu)*rstd*g4.x + be4.x; y = 0.5f*y*(1.0f + erff(y*ic)); u.x = f2tf32(y);
                y = (c.y - mu)*rstd*g4.y + be4.y; y = 0.5f*y*(1.0f + erff(y*ic)); u.y = f2tf32(y);
                y = (c.z - mu)*rstd*g4.z + be4.z; y = 0.5f*y*(1.0f + erff(y*ic)); u.z = f2tf32(y);
                y = (c.w - mu)*rstd*g4.w + be4.w; y = 0.5f*y*(1.0f + erff(y*ic)); u.w = f2tf32(y);
                ((uint4*)(Zu + m*PZ))[lane] = u;
            }
        } else {
            float* outp = (phase == 3) ? g_q : (phase == 4) ? g_k : g_v;
            for (int it = 0; it < 16; it++) {
                int m = w + 8*it;
                float4 c = ((const float4*)(Wsm + m*PW))[lane];
                float4 b4 = ((const float4*)bias_sm)[lane];
                c.x += b4.x; c.y += b4.y; c.z += b4.z; c.w += b4.w;
                ((float4*)(outp + ((size_t)(r0+m)*VV + v)*HH))[lane] = c;
            }
        }
    }
}

// ---------------- attention via mma.sync tf32, fused output head ----------------
__global__ void __launch_bounds__(256, 1) k_attn2(float* __restrict__ out) {
    __shared__ uint32_t Ks[SS*PK];   // 20KB, tf32 bits
    __shared__ uint32_t Vs[SS*PVT];  // 24KB, tf32 bits
    __shared__ float    wfs[HH];
    int bid  = blockIdx.x;
    int half = bid & 1;
    int v    = (bid >> 1) & (VV-1);
    int b    = bid >> 7;
    int tid  = threadIdx.x;
    int w    = tid >> 5, lane = tid & 31;
    int gid  = lane >> 2, qid = lane & 3;
    const size_t RSTR = (size_t)VV*HH;
    const size_t rowbase = ((size_t)(b*SS)*VV + v)*HH;

    if (tid < HH) wfs[tid] = g_wf[v*HH + tid];

    #pragma unroll 1
    for (int hh = 0; hh < 4; hh++) {
        int hbase = (half*4 + hh)*DHH;
        __syncthreads();   // protect prior head's Ks/Vs reads (and wfs on first iter)
        {
            const float* kp = g_k + rowbase + (size_t)tid*RSTR + hbase;
            const float* vp = g_v + rowbase + (size_t)tid*RSTR + hbase;
            #pragma unroll
            for (int c4 = 0; c4 < 4; c4++) {
                float4 kv = ((const float4*)kp)[c4];
                float4 vv = ((const float4*)vp)[c4];
                uint32_t* kd = Ks + tid*PK + 4*c4;
                uint32_t* vd = Vs + tid*PVT + 4*c4;
                kd[0] = f2tf32(kv.x); kd[1] = f2tf32(kv.y);
                kd[2] = f2tf32(kv.z); kd[3] = f2tf32(kv.w);
                vd[0] = f2tf32(vv.x); vd[1] = f2tf32(vv.y);
                vd[2] = f2tf32(vv.z); vd[3] = f2tf32(vv.w);
            }
        }
        __syncthreads();

        #pragma unroll 1
        for (int rep = 0; rep < 2; rep++) {
            int q0 = (w + 8*rep) * 16;
            uint32_t Aq[2][4];
            const float* qp = g_q + rowbase + (size_t)q0*RSTR + hbase;
            #pragma unroll
            for (int ks = 0; ks < 2; ks++) {
                int k0 = 8*ks;
                Aq[ks][0] = f2tf32(0.25f*qp[(size_t) gid   *RSTR + k0 + qid    ]);
                Aq[ks][1] = f2tf32(0.25f*qp[(size_t)(gid+8)*RSTR + k0 + qid    ]);
                Aq[ks][2] = f2tf32(0.25f*qp[(size_t) gid   *RSTR + k0 + qid + 4]);
                Aq[ks][3] = f2tf32(0.25f*qp[(size_t)(gid+8)*RSTR + k0 + qid + 4]);
            }
            float sacc[32][4];
            #pragma unroll
            for (int nt = 0; nt < 32; nt++)
                { sacc[nt][0]=0.f; sacc[nt][1]=0.f; sacc[nt][2]=0.f; sacc[nt][3]=0.f; }
            #pragma unroll
            for (int nt = 0; nt < 32; nt++) {
                #pragma unroll
                for (int ks = 0; ks < 2; ks++) {
                    uint32_t Bf[2];
                    const uint32_t* kp2 = Ks + (nt*8 + gid)*PK + 8*ks + qid;
                    Bf[0] = kp2[0];
                    Bf[1] = kp2[4];
                    mma_tf32(sacc[nt], Aq[ks], Bf);
                }
            }
            float m0 = -1e30f, m1 = -1e30f;
            #pragma unroll
            for (int nt = 0; nt < 32; nt++) {
                m0 = fmaxf(m0, fmaxf(sacc[nt][0], sacc[nt][1]));
                m1 = fmaxf(m1, fmaxf(sacc[nt][2], sacc[nt][3]));
            }
            m0 = fmaxf(m0, __shfl_xor_sync(0xffffffffu, m0, 1));
            m0 = fmaxf(m0, __shfl_xor_sync(0xffffffffu, m0, 2));
            m1 = fmaxf(m1, __shfl_xor_sync(0xffffffffu, m1, 1));
            m1 = fmaxf(m1, __shfl_xor_sync(0xffffffffu, m1, 2));
            float s0 = 0.f, s1 = 0.f;
            uint32_t* su = (uint32_t*)sacc;
            #pragma unroll
            for (int nt = 0; nt < 32; nt++) {
                float e0 = __expf(sacc[nt][0] - m0);
                float e1 = __expf(sacc[nt][1] - m0);
                float e2 = __expf(sacc[nt][2] - m1);
                float e3 = __expf(sacc[nt][3] - m1);
                s0 += e0 + e1; s1 += e2 + e3;
                su[4*nt+0] = f2tf32(e0); su[4*nt+1] = f2tf32(e1);
                su[4*nt+2] = f2tf32(e2); su[4*nt+3] = f2tf32(e3);
            }
            s0 += __shfl_xor_sync(0xffffffffu, s0, 1);
            s0 += __shfl_xor_sync(0xffffffffu, s0, 2);
            s1 += __shfl_xor_sync(0xffffffffu, s1, 1);
            s1 += __shfl_xor_sync(0xffffffffu, s1, 2);
            float inv0 = 1.0f/s0, inv1 = 1.0f/s1;
            float oacc[2][4];
            oacc[0][0]=0.f; oacc[0][1]=0.f; oacc[0][2]=0.f; oacc[0][3]=0.f;
            oacc[1][0]=0.f; oacc[1][1]=0.f; oacc[1][2]=0.f; oacc[1][3]=0.f;
            int src_lo = (lane & ~3) | (qid >> 1);
            int src_hi = src_lo + 2;
            int psel   = qid & 1;
            #pragma unroll
            for (int kc = 0; kc < 32; kc++) {
                uint32_t aP[4];
                uint32_t e0 = __shfl_sync(0xffffffffu, su[4*kc+0], src_lo);
                uint32_t e1 = __shfl_sync(0xffffffffu, su[4*kc+1], src_lo);
                aP[0] = psel ? e1 : e0;
                uint32_t g0 = __shfl_sync(0xffffffffu, su[4*kc+2], src_lo);
                uint32_t g1 = __shfl_sync(0xffffffffu, su[4*kc+3], src_lo);
                aP[1] = psel ? g1 : g0;
                uint32_t h0 = __shfl_sync(0xffffffffu, su[4*kc+0], src_hi);
                uint32_t h1 = __shfl_sync(0xffffffffu, su[4*kc+1], src_hi);
                aP[2] = psel ? h1 : h0;
                uint32_t i0 = __shfl_sync(0xffffffffu, su[4*kc+2], src_hi);
                uint32_t i1 = __shfl_sync(0xffffffffu, su[4*kc+3], src_hi);
                aP[3] = psel ? i1 : i0;
                #pragma unroll
                for (int nt2 = 0; nt2 < 2; nt2++) {
                    uint32_t Bv[2];
                    const uint32_t* vp2 = Vs + (kc*8 + qid)*PVT + nt2*8 + gid;
                    Bv[0] = vp2[0];
                    Bv[1] = vp2[4*PVT];
                    mma_tf32(oacc[nt2], aP, Bv);
                }
            }
            // ---- fused output head: partial = (o . wf[hbase..]) per row ----
            float plo = 0.f, phi = 0.f;
            #pragma unroll
            for (int nt2 = 0; nt2 < 2; nt2++) {
                float w0 = wfs[hbase + nt2*8 + 2*qid];
                float w1 = wfs[hbase + nt2*8 + 2*qid + 1];
                plo = fmaf(oacc[nt2][0], w0, fmaf(oacc[nt2][1], w1, plo));
                phi = fmaf(oacc[nt2][2], w0, fmaf(oacc[nt2][3], w1, phi));
            }
            plo *= inv0; phi *= inv1;
            plo += __shfl_xor_sync(0xffffffffu, plo, 1);
            plo += __shfl_xor_sync(0xffffffffu, plo, 2);
            phi += __shfl_xor_sync(0xffffffffu, phi, 1);
            phi += __shfl_xor_sync(0xffffffffu, phi, 2);
            if (qid == 0) {
                atomicAdd(out + ((size_t)(b*SS + q0 + gid    )*VV + v), plo);
                atomicAdd(out + ((size_t)(b*SS + q0 + gid + 8)*VV + v), phi);
            }
        }
    }
}

// ---------------- launch ----------------
extern "C" void kernel_launch(void* const* d_in, const int* in_sizes, int n_in,
                              void* d_out, int out_size) {
    (void)in_sizes; (void)n_in; (void)out_size;
    const float* x        = (const float*)d_in[0];
    const float* adjl     = (const float*)d_in[1];
    const float* var_emb  = (const float*)d_in[2];
    const float* temp_emb = (const float*)d_in[3];
    const float* mech_W   = (const float*)d_in[4];
    const float* mech_b   = (const float*)d_in[5];
    const float* ln_g     = (const float*)d_in[6];
    const float* ln_b     = (const float*)d_in[7];
    const float* Wq       = (const float*)d_in[8];
    const float* Wk       = (const float*)d_in[9];
    const float* Wv       = (const float*)d_in[10];
    const float* Wo       = (const float*)d_in[11];
    const float* bq       = (const float*)d_in[12];
    const float* bk       = (const float*)d_in[13];
    const float* bv       = (const float*)d_in[14];
    const float* bo       = (const float*)d_in[15];
    const float* outW     = (const float*)d_in[16];
    const float* outb     = (const float*)d_in[17];
    float* out = (float*)d_out;

    const int SMEM_LAG   = (SS*VV + VV*LL)*4;
    const int SMEM_TRANS = HH*129*4;
    const int SMEM_CHAIN = (HH*PW + HH*PZ + 3*HH)*4;
    cudaFuncSetAttribute(k_lagmix,    cudaFuncAttributeMaxDynamicSharedMemorySize, SMEM_LAG);
    cudaFuncSetAttribute(k_transpose, cudaFuncAttributeMaxDynamicSharedMemorySize, SMEM_TRANS);
    cudaFuncSetAttribute(k_chain,     cudaFuncAttributeMaxDynamicSharedMemorySize, SMEM_CHAIN);

    const int N_PREP = VV*VV*LL + HH*KAB + VV;   // 55360
    k_prep<<<(N_PREP + 255)/256, 256>>>(adjl, var_emb, temp_emb, outW, bo, outb);
    k_prepwf<<<VV*HH/8, 256>>>(Wo, outW);
    k_transpose<<<6*VV, 256, SMEM_TRANS>>>(mech_W, Wq, Wk, Wv);
    k_lagmix<<<BB*VV, 256, SMEM_LAG>>>(x);

    dim3 gchain(BS/128, VV);   // (8, 64)
    k_chain<<<gchain, 256, SMEM_CHAIN>>>(mech_b, ln_g, ln_b, bq, bk, bv);

    k_initout<<<NROWS/256, 256>>>(out);
    k_attn2<<<BB*VV*2, 256>>>(out);
}

// round 16
// speedup vs baseline: 2.2491x; 1.0401x over previous
#include <cuda_runtime.h>
#include <math.h>
#include <stdint.h>

#define BB 4
#define SS 256
#define VV 64
#define LL 11            // L+1
#define HH 128
#define NHH 8
#define DHH 16
#define NLL 3
#define BS (BB*SS)       // 1024
#define NROWS (BB*SS*VV) // 65536
#define KAB 80           // 64 (A) + 11 (Bl) + 5 pad

// smem pitches (floats) chosen for conflict-free mma fragment access
#define PW 136           // Wsm: bank = 8n + k  -> distinct over (n:8, k:4)
#define PZ 132           // Zsm: bank = 4m + k  -> distinct over (m:8, k:4)
#define PK 20            // attn K: bank = 20*gid + qid -> all 32 distinct
#define PVT 24           // attn V: bank = 24*qid + gid -> all 32 distinct
#define PX 68            // x slab pitch (float4-aligned, bank-staggered)

// ---------------- device scratch ----------------
__device__ float g_adj[VV*VV*LL];
__device__ float g_Et[HH*KAB];    // E^T[n][k], tf32 bits
__device__ float g_wf[VV*HH];
__device__ float g_bf[VV];
__device__ float g_q [NROWS*HH];
__device__ float g_k [NROWS*HH];
__device__ float g_v [NROWS*HH];
// transposed (W^T[n][k]) + tf32-rounded weights: [6 mats][64 v][128*128]
__device__ float g_Wt[6*VV*HH*HH];

// ---------------- helpers ----------------
__device__ __forceinline__ uint32_t f2tf32(float x) {
    uint32_t r; asm("cvt.rna.tf32.f32 %0, %1;" : "=r"(r) : "f"(x)); return r;
}
__device__ __forceinline__ void mma_tf32(float* c, const uint32_t* a, const uint32_t* b) {
    asm volatile(
        "mma.sync.aligned.m16n8k8.row.col.f32.tf32.tf32.f32 "
        "{%0,%1,%2,%3}, {%4,%5,%6,%7}, {%8,%9}, {%0,%1,%2,%3};"
        : "+f"(c[0]), "+f"(c[1]), "+f"(c[2]), "+f"(c[3])
        : "r"(a[0]), "r"(a[1]), "r"(a[2]), "r"(a[3]), "r"(b[0]), "r"(b[1]));
}

// ---------------- prep: sigmoid(adj), E^T (tf32), bf ----------------
__global__ void k_prep(const float* __restrict__ adjl,
                       const float* __restrict__ var_emb,
                       const float* __restrict__ temp_emb,
                       const float* __restrict__ outW,
                       const float* __restrict__ bo,
                       const float* __restrict__ outb) {
    int idx = blockIdx.x*blockDim.x + threadIdx.x;
    const int N_ADJ = VV*VV*LL;      // 45056
    const int N_ET  = HH*KAB;        // 10240
    if (idx < N_ADJ) {
        g_adj[idx] = 1.0f/(1.0f + __expf(-adjl[idx]));
    } else if (idx < N_ADJ + N_ET) {
        int t = idx - N_ADJ;
        int n = t / KAB, k = t % KAB;
        float val = 0.0f;
        if (k < VV)          val = var_emb[k*HH + n];
        else if (k < VV+LL)  val = temp_emb[(k-VV)*HH + n];
        g_Et[n*KAB + k] = __uint_as_float(f2tf32(val));
    } else if (idx < N_ADJ + N_ET + VV) {
        int v = idx - N_ADJ - N_ET;
        float acc = outb[v];
        for (int k = 0; k < HH; k++) acc = fmaf(bo[v*HH+k], outW[v*HH+k], acc);
        g_bf[v] = acc;
    }
}

// ---------------- prep: wf[v][h] = Wo[v][h][:] . outW[v][:], warp per output ----------------
__global__ void __launch_bounds__(256) k_prepwf(const float* __restrict__ Wo,
                                                const float* __restrict__ outW) {
    int w = threadIdx.x >> 5, lane = threadIdx.x & 31;
    int r = blockIdx.x*8 + w;          // r = v*128 + h, 8192 total
    int v = r >> 7;
    float4 a = ((const float4*)(Wo + (size_t)r*HH))[lane];
    float4 b = ((const float4*)(outW + v*HH))[lane];
    float p = a.x*b.x + a.y*b.y + a.z*b.z + a.w*b.w;
    #pragma unroll
    for (int off = 16; off; off >>= 1) p += __shfl_xor_sync(0xffffffffu, p, off);
    if (lane == 0) g_wf[r] = p;
}

// ---------------- init out with bf ----------------
__global__ void k_initout(float* __restrict__ out) {
    int idx = blockIdx.x*blockDim.x + threadIdx.x;
    out[idx] = g_bf[idx & (VV-1)];
}

// ---------------- transpose + tf32-round the 6 weight sets: g_Wt[n][k] = W[k][n] ----------------
__global__ void __launch_bounds__(256) k_transpose(const float* __restrict__ mechW,
        const float* __restrict__ Wq, const float* __restrict__ Wk, const float* __restrict__ Wv) {
    extern __shared__ float sm[];     // 128 x 129 floats
    int mat = blockIdx.x >> 6;        // 0..5
    int v   = blockIdx.x & 63;
    const float* src;
    if (mat < 3)       src = mechW + ((size_t)v*NLL + mat)*HH*HH;
    else if (mat == 3) src = Wq + (size_t)v*HH*HH;
    else if (mat == 4) src = Wk + (size_t)v*HH*HH;
    else               src = Wv + (size_t)v*HH*HH;
    float* dst = g_Wt + ((size_t)mat*VV + v)*HH*HH;
    int tid = threadIdx.x;
    for (int idx = tid; idx < HH*HH/4; idx += 256) {
        int k = idx >> 5, c4 = idx & 31;
        float4 w = ((const float4*)src)[idx];
        float* p = sm + k*129 + 4*c4;
        p[0]=w.x; p[1]=w.y; p[2]=w.z; p[3]=w.w;
    }
    __syncthreads();
    for (int idx = tid; idx < HH*HH/4; idx += 256) {
        int n = idx >> 5, k4 = idx & 31;
        int k = 4*k4;
        uint4 u;
        u.x = f2tf32(sm[(k+0)*129 + n]);
        u.y = f2tf32(sm[(k+1)*129 + n]);
        u.z = f2tf32(sm[(k+2)*129 + n]);
        u.w = f2tf32(sm[(k+3)*129 + n]);
        ((uint4*)(dst + n*HH))[k4] = u;
    }
}

// ---------------- fused lagmix + embed + mech x3 + QKV chain via mma.sync tf32 ----------------
// CTA = (row-tile of 128, variable v); 256 threads (8 warps).
// stage 0: in-CTA lag-mix -> AB directly in Zsm (tf32)
// phase -1: z = AB @ E  (A-operand = E^T in Wsm, K=80)
// phases 0..5: out^T[n][m] = W^T[n][k] * z[m][k], LN+GELU / bias epilogues.
__global__ void __launch_bounds__(256, 1) k_chain(const float* __restrict__ x,
        const float* __restrict__ mech_b,
        const float* __restrict__ ln_g, const float* __restrict__ ln_b,
        const float* __restrict__ bqv, const float* __restrict__ bkv,
        const float* __restrict__ bvv) {
    extern __shared__ float smf[];
    float* Wsm = smf;                         // 128 x PW floats (also C' staging / x slab)
    float* Zsm = smf + HH*PW;                 // 128 x PZ floats
    float* bias_sm = smf + HH*PW + HH*PZ;     // 128
    float* g_sm    = bias_sm + HH;            // 128
    float* be_sm   = g_sm + HH;               // 128
    float* adj_sm  = be_sm + HH;              // 64*11 = 704
    uint32_t* Wu = (uint32_t*)Wsm;
    uint32_t* Zu = (uint32_t*)Zsm;

    int tid  = threadIdx.x;
    int w    = tid >> 5, lane = tid & 31;
    int gid  = lane >> 2, qid = lane & 3;
    int v    = blockIdx.y;
    int r0   = blockIdx.x * 128;
    int n0   = (w & 1) * 64;
    int m0   = (w >> 1) * 32;

    // ======== stage 0: in-CTA lag-mix -> Zsm ========
    {
        float* Xsm = Wsm;                     // 138 x PX floats = 37.5KB, fits in Wsm
        int b  = r0 >> 8;
        int t0 = r0 & 255;
        // load x rows [t0-10 .. t0+127] (zero rows for t<0)
        #pragma unroll
        for (int i = 0; i < 9; i++) {
            int idx = tid + 256*i;            // 138*16 = 2208 float4
            if (idx < 138*16) {
                int row = idx >> 4, c4 = idx & 15;
                int t = t0 - 10 + row;
                float4 val = make_float4(0.f,0.f,0.f,0.f);
                if (t >= 0) val = ((const float4*)(x + ((size_t)b*SS + t)*VV))[c4];
                ((float4*)(Xsm + row*PX))[c4] = val;
            }
        }
        // load adjacency slice for v: adj_sm[s*11 + l] = sigmoid(adj)[s, v, l]
        for (int p = tid; p < VV*LL; p += 256) {
            int s = p / LL, l = p % LL;
            adj_sm[p] = g_adj[(s*VV + v)*LL + l];
        }
        __syncthreads();
        // A part: thread = (s = tid&63, mg = tid>>6); A[m][s] = sum_l x[t0+m-l][s]*adj[s][l]
        {
            int s  = tid & 63;
            int mg = tid >> 6;
            float a[LL];
            #pragma unroll
            for (int l = 0; l < LL; l++) a[l] = adj_sm[s*LL + l];
            for (int m = mg; m < 128; m += 4) {
                const float* xcol = Xsm + (m + 10)*PX + s;
                float acc = 0.0f;
                #pragma unroll
                for (int l = 0; l < LL; l++)
                    acc = fmaf(xcol[-l*PX], a[l], acc);
                Zu[m*PZ + s] = f2tf32(acc);
            }
        }
        // Bl part: thread per (m,l); Bl[m][l] = sum_s x[t0+m-l][s]*adj[s][l]
        for (int idx = tid; idx < 128*LL; idx += 256) {
            int m = idx / LL, l = idx % LL;
            const float* xr = Xsm + (m + 10 - l)*PX;
            float acc = 0.0f;
            #pragma unroll 16
            for (int s = 0; s < VV; s++)
                acc = fmaf(xr[s], adj_sm[s*LL + l], acc);
            Zu[m*PZ + VV + l] = f2tf32(acc);
        }
        // zero pad k-slots 75..79
        for (int idx = tid; idx < 128*5; idx += 256) {
            int m = idx / 5, j = idx % 5;
            Zu[m*PZ + VV + LL + j] = 0u;
        }
        __syncthreads();   // Xsm fully consumed before E^T overwrites Wsm
    }

    // ======== phase -1: embed z = AB @ E ========
    // load E^T (128 x 80 tf32 bits) into Wsm
    #pragma unroll
    for (int i = 0; i < 10; i++) {
        int idx = tid + 256*i;        // 2560 float4 = 128 rows x 20
        int n = idx / 20, k4 = idx % 20;
        ((float4*)(Wsm + n*PW))[k4] = ((const float4*)g_Et)[idx];
    }
    __syncthreads();
    {
        float acc[4][4][4];
        #pragma unroll
        for (int nt = 0; nt < 4; nt++)
            #pragma unroll
            for (int mt = 0; mt < 4; mt++)
                #pragma unroll
                for (int r = 0; r < 4; r++) acc[nt][mt][r] = 0.0f;
        #pragma unroll 2
        for (int s = 0; s < 10; s++) {
            int k0 = 8*s;
            uint32_t Af[4][4], Bf[4][2];
            #pragma unroll
            for (int nt = 0; nt < 4; nt++) {
                const uint32_t* p = Wu + (n0 + nt*16 + gid)*PW + k0 + qid;
                Af[nt][0] = p[0];
                Af[nt][1] = p[8*PW];
                Af[nt][2] = p[4];
                Af[nt][3] = p[8*PW + 4];
            }
            #pragma unroll
            for (int mt = 0; mt < 4; mt++) {
                const uint32_t* q = Zu + (m0 + mt*8 + gid)*PZ + k0 + qid;
                Bf[mt][0] = q[0];
                Bf[mt][1] = q[4];
            }
            #pragma unroll
            for (int nt = 0; nt < 4; nt++)
                #pragma unroll
                for (int mt = 0; mt < 4; mt++)
                    mma_tf32(acc[nt][mt], Af[nt], Bf[mt]);
        }
        __syncthreads();   // done reading Wsm/Zsm -> stage C'
        #pragma unroll
        for (int nt = 0; nt < 4; nt++) {
            int nb = n0 + nt*16 + gid;
            #pragma unroll
            for (int mt = 0; mt < 4; mt++) {
                int mb = m0 + mt*8 + 2*qid;
                Wsm[ mb   *PW + nb    ] = acc[nt][mt][0];
                Wsm[(mb+1)*PW + nb    ] = acc[nt][mt][1];
                Wsm[ mb   *PW + nb + 8] = acc[nt][mt][2];
                Wsm[(mb+1)*PW + nb + 8] = acc[nt][mt][3];
            }
        }
        __syncthreads();
        // epilogue: z (tf32) into Zsm, no bias/LN
        for (int it = 0; it < 16; it++) {
            int m = w + 8*it;
            float4 c = ((const float4*)(Wsm + m*PW))[lane];
            uint4 u; u.x=f2tf32(c.x); u.y=f2tf32(c.y); u.z=f2tf32(c.z); u.w=f2tf32(c.w);
            ((uint4*)(Zu + m*PZ))[lane] = u;
        }
    }

    // ======== phases 0..5 ========
    #pragma unroll 1
    for (int phase = 0; phase < 6; phase++) {
        __syncthreads();
        {
            const float4* src = (const float4*)(g_Wt + ((size_t)phase*VV + v)*HH*HH);
            #pragma unroll
            for (int i = 0; i < 16; i++) {
                int idx = tid + 256*i;
                int n = idx >> 5, k4 = idx & 31;
                ((float4*)(Wsm + n*PW))[k4] = src[idx];
            }
        }
        if (tid < HH) {
            if (phase < 3) {
                bias_sm[tid] = mech_b[((size_t)v*NLL + phase)*HH + tid];
                g_sm[tid]    = ln_g  [((size_t)v*NLL + phase)*HH + tid];
                be_sm[tid]   = ln_b  [((size_t)v*NLL + phase)*HH + tid];
            } else {
                const float* bp = (phase == 3) ? bqv : (phase == 4) ? bkv : bvv;
                bias_sm[tid] = bp[v*HH + tid];
            }
        }
        __syncthreads();

        float acc[4][4][4];
        #pragma unroll
        for (int nt = 0; nt < 4; nt++)
            #pragma unroll
            for (int mt = 0; mt < 4; mt++)
                #pragma unroll
                for (int r = 0; r < 4; r++) acc[nt][mt][r] = 0.0f;

        #pragma unroll 4
        for (int s = 0; s < 16; s++) {
            int k0 = 8*s;
            uint32_t Af[4][4], Bf[4][2];
            #pragma unroll
            for (int nt = 0; nt < 4; nt++) {
                const uint32_t* p = Wu + (n0 + nt*16 + gid)*PW + k0 + qid;
                Af[nt][0] = p[0];
                Af[nt][1] = p[8*PW];
                Af[nt][2] = p[4];
                Af[nt][3] = p[8*PW + 4];
            }
            #pragma unroll
            for (int mt = 0; mt < 4; mt++) {
                const uint32_t* q = Zu + (m0 + mt*8 + gid)*PZ + k0 + qid;
                Bf[mt][0] = q[0];
                Bf[mt][1] = q[4];
            }
            #pragma unroll
            for (int nt = 0; nt < 4; nt++)
                #pragma unroll
                for (int mt = 0; mt < 4; mt++)
                    mma_tf32(acc[nt][mt], Af[nt], Bf[mt]);
        }
        __syncthreads();

        #pragma unroll
        for (int nt = 0; nt < 4; nt++) {
            int nb = n0 + nt*16 + gid;
            #pragma unroll
            for (int mt = 0; mt < 4; mt++) {
                int mb = m0 + mt*8 + 2*qid;
                Wsm[ mb   *PW + nb    ] = acc[nt][mt][0];
                Wsm[(mb+1)*PW + nb    ] = acc[nt][mt][1];
                Wsm[ mb   *PW + nb + 8] = acc[nt][mt][2];
                Wsm[(mb+1)*PW + nb + 8] = acc[nt][mt][3];
            }
        }
        __syncthreads();

        if (phase < 3) {
            for (int it = 0; it < 16; it++) {
                int m = w + 8*it;
                float4 c = ((const float4*)(Wsm + m*PW))[lane];
                float4 b4 = ((const float4*)bias_sm)[lane];
                c.x += b4.x; c.y += b4.y; c.z += b4.z; c.w += b4.w;
                float s  = c.x + c.y + c.z + c.w;
                float ss = c.x*c.x + c.y*c.y + c.z*c.z + c.w*c.w;
                #pragma unroll
                for (int off = 16; off; off >>= 1) {
                    s  += __shfl_xor_sync(0xffffffffu, s,  off);
                    ss += __shfl_xor_sync(0xffffffffu, ss, off);
                }
                float mu   = s * (1.0f/128.0f);
                float var  = ss * (1.0f/128.0f) - mu*mu;
                float rstd = rsqrtf(var + 1e-5f);
                float4 g4  = ((const float4*)g_sm)[lane];
                float4 be4 = ((const float4*)be_sm)[lane];
                const float ic = 0.70710678118654752440f;
                float y;
                uint4 u;
                y = (c.x - mu)*rstd*g4.x + be4.x; y = 0.5f*y*(1.0f + erff(y*ic)); u.x = f2tf32(y);
                y = (c.y - mu)*rstd*g4.y + be4.y; y = 0.5f*y*(1.0f + erff(y*ic)); u.y = f2tf32(y);
                y = (c.z - mu)*rstd*g4.z + be4.z; y = 0.5f*y*(1.0f + erff(y*ic)); u.z = f2tf32(y);
                y = (c.w - mu)*rstd*g4.w + be4.w; y = 0.5f*y*(1.0f + erff(y*ic)); u.w = f2tf32(y);
                ((uint4*)(Zu + m*PZ))[lane] = u;
            }
        } else {
            float* outp = (phase == 3) ? g_q : (phase == 4) ? g_k : g_v;
            for (int it = 0; it < 16; it++) {
                int m = w + 8*it;
                float4 c = ((const float4*)(Wsm + m*PW))[lane];
                float4 b4 = ((const float4*)bias_sm)[lane];
                c.x += b4.x; c.y += b4.y; c.z += b4.z; c.w += b4.w;
                ((float4*)(outp + ((size_t)(r0+m)*VV + v)*HH))[lane] = c;
            }
        }
    }
}

// ---------------- attention via mma.sync tf32, fused output head ----------------
__global__ void __launch_bounds__(256, 1) k_attn2(float* __restrict__ out) {
    __shared__ uint32_t Ks[SS*PK];   // 20KB, tf32 bits
    __shared__ uint32_t Vs[SS*PVT];  // 24KB, tf32 bits
    __shared__ float    wfs[HH];
    int bid  = blockIdx.x;
    int half = bid & 1;
    int v    = (bid >> 1) & (VV-1);
    int b    = bid >> 7;
    int tid  = threadIdx.x;
    int w    = tid >> 5, lane = tid & 31;
    int gid  = lane >> 2, qid = lane & 3;
    const size_t RSTR = (size_t)VV*HH;
    const size_t rowbase = ((size_t)(b*SS)*VV + v)*HH;

    if (tid < HH) wfs[tid] = g_wf[v*HH + tid];

    #pragma unroll 1
    for (int hh = 0; hh < 4; hh++) {
        int hbase = (half*4 + hh)*DHH;
        __syncthreads();   // protect prior head's Ks/Vs reads (and wfs on first iter)
        {
            const float* kp = g_k + rowbase + (size_t)tid*RSTR + hbase;
            const float* vp = g_v + rowbase + (size_t)tid*RSTR + hbase;
            #pragma unroll
            for (int c4 = 0; c4 < 4; c4++) {
                float4 kv = ((const float4*)kp)[c4];
                float4 vv = ((const float4*)vp)[c4];
                uint32_t* kd = Ks + tid*PK + 4*c4;
                uint32_t* vd = Vs + tid*PVT + 4*c4;
                kd[0] = f2tf32(kv.x); kd[1] = f2tf32(kv.y);
                kd[2] = f2tf32(kv.z); kd[3] = f2tf32(kv.w);
                vd[0] = f2tf32(vv.x); vd[1] = f2tf32(vv.y);
                vd[2] = f2tf32(vv.z); vd[3] = f2tf32(vv.w);
            }
        }
        __syncthreads();

        #pragma unroll 1
        for (int rep = 0; rep < 2; rep++) {
            int q0 = (w + 8*rep) * 16;
            uint32_t Aq[2][4];
            const float* qp = g_q + rowbase + (size_t)q0*RSTR + hbase;
            #pragma unroll
            for (int ks = 0; ks < 2; ks++) {
                int k0 = 8*ks;
                Aq[ks][0] = f2tf32(0.25f*qp[(size_t) gid   *RSTR + k0 + qid    ]);
                Aq[ks][1] = f2tf32(0.25f*qp[(size_t)(gid+8)*RSTR + k0 + qid    ]);
                Aq[ks][2] = f2tf32(0.25f*qp[(size_t) gid   *RSTR + k0 + qid + 4]);
                Aq[ks][3] = f2tf32(0.25f*qp[(size_t)(gid+8)*RSTR + k0 + qid + 4]);
            }
            float sacc[32][4];
            #pragma unroll
            for (int nt = 0; nt < 32; nt++)
                { sacc[nt][0]=0.f; sacc[nt][1]=0.f; sacc[nt][2]=0.f; sacc[nt][3]=0.f; }
            #pragma unroll
            for (int nt = 0; nt < 32; nt++) {
                #pragma unroll
                for (int ks = 0; ks < 2; ks++) {
                    uint32_t Bf[2];
                    const uint32_t* kp2 = Ks + (nt*8 + gid)*PK + 8*ks + qid;
                    Bf[0] = kp2[0];
                    Bf[1] = kp2[4];
                    mma_tf32(sacc[nt], Aq[ks], Bf);
                }
            }
            float m0 = -1e30f, m1 = -1e30f;
            #pragma unroll
            for (int nt = 0; nt < 32; nt++) {
                m0 = fmaxf(m0, fmaxf(sacc[nt][0], sacc[nt][1]));
                m1 = fmaxf(m1, fmaxf(sacc[nt][2], sacc[nt][3]));
            }
            m0 = fmaxf(m0, __shfl_xor_sync(0xffffffffu, m0, 1));
            m0 = fmaxf(m0, __shfl_xor_sync(0xffffffffu, m0, 2));
            m1 = fmaxf(m1, __shfl_xor_sync(0xffffffffu, m1, 1));
            m1 = fmaxf(m1, __shfl_xor_sync(0xffffffffu, m1, 2));
            float s0 = 0.f, s1 = 0.f;
            uint32_t* su = (uint32_t*)sacc;
            #pragma unroll
            for (int nt = 0; nt < 32; nt++) {
                float e0 = __expf(sacc[nt][0] - m0);
                float e1 = __expf(sacc[nt][1] - m0);
                float e2 = __expf(sacc[nt][2] - m1);
                float e3 = __expf(sacc[nt][3] - m1);
                s0 += e0 + e1; s1 += e2 + e3;
                su[4*nt+0] = f2tf32(e0); su[4*nt+1] = f2tf32(e1);
                su[4*nt+2] = f2tf32(e2); su[4*nt+3] = f2tf32(e3);
            }
            s0 += __shfl_xor_sync(0xffffffffu, s0, 1);
            s0 += __shfl_xor_sync(0xffffffffu, s0, 2);
            s1 += __shfl_xor_sync(0xffffffffu, s1, 1);
            s1 += __shfl_xor_sync(0xffffffffu, s1, 2);
            float inv0 = 1.0f/s0, inv1 = 1.0f/s1;
            float oacc[2][4];
            oacc[0][0]=0.f; oacc[0][1]=0.f; oacc[0][2]=0.f; oacc[0][3]=0.f;
            oacc[1][0]=0.f; oacc[1][1]=0.f; oacc[1][2]=0.f; oacc[1][3]=0.f;
            int src_lo = (lane & ~3) | (qid >> 1);
            int src_hi = src_lo + 2;
            int psel   = qid & 1;
            #pragma unroll
            for (int kc = 0; kc < 32; kc++) {
                uint32_t aP[4];
                uint32_t e0 = __shfl_sync(0xffffffffu, su[4*kc+0], src_lo);
                uint32_t e1 = __shfl_sync(0xffffffffu, su[4*kc+1], src_lo);
                aP[0] = psel ? e1 : e0;
                uint32_t g0 = __shfl_sync(0xffffffffu, su[4*kc+2], src_lo);
                uint32_t g1 = __shfl_sync(0xffffffffu, su[4*kc+3], src_lo);
                aP[1] = psel ? g1 : g0;
                uint32_t h0 = __shfl_sync(0xffffffffu, su[4*kc+0], src_hi);
                uint32_t h1 = __shfl_sync(0xffffffffu, su[4*kc+1], src_hi);
                aP[2] = psel ? h1 : h0;
                uint32_t i0 = __shfl_sync(0xffffffffu, su[4*kc+2], src_hi);
                uint32_t i1 = __shfl_sync(0xffffffffu, su[4*kc+3], src_hi);
                aP[3] = psel ? i1 : i0;
                #pragma unroll
                for (int nt2 = 0; nt2 < 2; nt2++) {
                    uint32_t Bv[2];
                    const uint32_t* vp2 = Vs + (kc*8 + qid)*PVT + nt2*8 + gid;
                    Bv[0] = vp2[0];
                    Bv[1] = vp2[4*PVT];
                    mma_tf32(oacc[nt2], aP, Bv);
                }
            }
            // ---- fused output head: partial = (o . wf[hbase..]) per row ----
            float plo = 0.f, phi = 0.f;
            #pragma unroll
            for (int nt2 = 0; nt2 < 2; nt2++) {
                float w0 = wfs[hbase + nt2*8 + 2*qid];
                float w1 = wfs[hbase + nt2*8 + 2*qid + 1];
                plo = fmaf(oacc[nt2][0], w0, fmaf(oacc[nt2][1], w1, plo));
                phi = fmaf(oacc[nt2][2], w0, fmaf(oacc[nt2][3], w1, phi));
            }
            plo *= inv0; phi *= inv1;
            plo += __shfl_xor_sync(0xffffffffu, plo, 1);
            plo += __shfl_xor_sync(0xffffffffu, plo, 2);
            phi += __shfl_xor_sync(0xffffffffu, phi, 1);
            phi += __shfl_xor_sync(0xffffffffu, phi, 2);
            if (qid == 0) {
                atomicAdd(out + ((size_t)(b*SS + q0 + gid    )*VV + v), plo);
                atomicAdd(out + ((size_t)(b*SS + q0 + gid + 8)*VV + v), phi);
            }
        }
    }
}

// ---------------- launch ----------------
extern "C" void kernel_launch(void* const* d_in, const int* in_sizes, int n_in,
                              void* d_out, int out_size) {
    (void)in_sizes; (void)n_in; (void)out_size;
    const float* x        = (const float*)d_in[0];
    const float* adjl     = (const float*)d_in[1];
    const float* var_emb  = (const float*)d_in[2];
    const float* temp_emb = (const float*)d_in[3];
    const float* mech_W   = (const float*)d_in[4];
    const float* mech_b   = (const float*)d_in[5];
    const float* ln_g     = (const float*)d_in[6];
    const float* ln_b     = (const float*)d_in[7];
    const float* Wq       = (const float*)d_in[8];
    const float* Wk       = (const float*)d_in[9];
    const float* Wv       = (const float*)d_in[10];
    const float* Wo       = (const float*)d_in[11];
    const float* bq       = (const float*)d_in[12];
    const float* bk       = (const float*)d_in[13];
    const float* bv       = (const float*)d_in[14];
    const float* bo       = (const float*)d_in[15];
    const float* outW     = (const float*)d_in[16];
    const float* outb     = (const float*)d_in[17];
    float* out = (float*)d_out;

    const int SMEM_TRANS = HH*129*4;
    const int SMEM_CHAIN = (HH*PW + HH*PZ + 3*HH + VV*LL)*4;   // 141568
    cudaFuncSetAttribute(k_transpose, cudaFuncAttributeMaxDynamicSharedMemorySize, SMEM_TRANS);
    cudaFuncSetAttribute(k_chain,     cudaFuncAttributeMaxDynamicSharedMemorySize, SMEM_CHAIN);

    const int N_PREP = VV*VV*LL + HH*KAB + VV;   // 55360
    k_prep<<<(N_PREP + 255)/256, 256>>>(adjl, var_emb, temp_emb, outW, bo, outb);
    k_prepwf<<<VV*HH/8, 256>>>(Wo, outW);
    k_transpose<<<6*VV, 256, SMEM_TRANS>>>(mech_W, Wq, Wk, Wv);

    dim3 gchain(BS/128, VV);   // (8, 64)
    k_chain<<<gchain, 256, SMEM_CHAIN>>>(x, mech_b, ln_g, ln_b, bq, bk, bv);

    k_initout<<<NROWS/256, 256>>>(out);
    k_attn2<<<BB*VV*2, 256>>>(out);
}

// round 17
// speedup vs baseline: 2.2606x; 1.0051x over previous
#include <cuda_runtime.h>
#include <math.h>
#include <stdint.h>

#define BB 4
#define SS 256
#define VV 64
#define LL 11            // L+1
#define HH 128
#define NHH 8
#define DHH 16
#define NLL 3
#define BS (BB*SS)       // 1024
#define NROWS (BB*SS*VV) // 65536
#define KAB 80           // 64 (A) + 11 (Bl) + 5 pad
#define MT 64            // chain row-tile

// smem pitches (floats) chosen for conflict-free mma fragment access
#define PW 136           // Wsm: bank = 8n + k  -> distinct over (n:8, k:4)
#define PZ 132           // Zsm: bank = 4m + k  -> distinct over (m:8, k:4)
#define PK 20            // attn K: bank = 20*gid + qid -> all 32 distinct
#define PVT 24           // attn V: bank = 24*qid + gid -> all 32 distinct
#define PX 68            // x slab pitch (float4-aligned, bank-staggered)

// ---------------- device scratch ----------------
__device__ float g_adj[VV*VV*LL];
__device__ float g_Et[HH*KAB];    // E^T[n][k], tf32 bits
__device__ float g_wf[VV*HH];
__device__ float g_bf[VV];
__device__ float g_q [NROWS*HH];
__device__ float g_k [NROWS*HH];
__device__ float g_v [NROWS*HH];
// transposed (W^T[n][k]) + tf32-rounded weights: [6 mats][64 v][128*128]
__device__ float g_Wt[6*VV*HH*HH];

// ---------------- helpers ----------------
__device__ __forceinline__ uint32_t f2tf32(float x) {
    uint32_t r; asm("cvt.rna.tf32.f32 %0, %1;" : "=r"(r) : "f"(x)); return r;
}
__device__ __forceinline__ void mma_tf32(float* c, const uint32_t* a, const uint32_t* b) {
    asm volatile(
        "mma.sync.aligned.m16n8k8.row.col.f32.tf32.tf32.f32 "
        "{%0,%1,%2,%3}, {%4,%5,%6,%7}, {%8,%9}, {%0,%1,%2,%3};"
        : "+f"(c[0]), "+f"(c[1]), "+f"(c[2]), "+f"(c[3])
        : "r"(a[0]), "r"(a[1]), "r"(a[2]), "r"(a[3]), "r"(b[0]), "r"(b[1]));
}

// ---------------- prep: sigmoid(adj), E^T (tf32), bf ----------------
__global__ void k_prep(const float* __restrict__ adjl,
                       const float* __restrict__ var_emb,
                       const float* __restrict__ temp_emb,
                       const float* __restrict__ outW,
                       const float* __restrict__ bo,
                       const float* __restrict__ outb) {
    int idx = blockIdx.x*blockDim.x + threadIdx.x;
    const int N_ADJ = VV*VV*LL;      // 45056
    const int N_ET  = HH*KAB;        // 10240
    if (idx < N_ADJ) {
        g_adj[idx] = 1.0f/(1.0f + __expf(-adjl[idx]));
    } else if (idx < N_ADJ + N_ET) {
        int t = idx - N_ADJ;
        int n = t / KAB, k = t % KAB;
        float val = 0.0f;
        if (k < VV)          val = var_emb[k*HH + n];
        else if (k < VV+LL)  val = temp_emb[(k-VV)*HH + n];
        g_Et[n*KAB + k] = __uint_as_float(f2tf32(val));
    } else if (idx < N_ADJ + N_ET + VV) {
        int v = idx - N_ADJ - N_ET;
        float acc = outb[v];
        for (int k = 0; k < HH; k++) acc = fmaf(bo[v*HH+k], outW[v*HH+k], acc);
        g_bf[v] = acc;
    }
}

// ---------------- prep: wf[v][h] = Wo[v][h][:] . outW[v][:], warp per output ----------------
__global__ void __launch_bounds__(256) k_prepwf(const float* __restrict__ Wo,
                                                const float* __restrict__ outW) {
    int w = threadIdx.x >> 5, lane = threadIdx.x & 31;
    int r = blockIdx.x*8 + w;          // r = v*128 + h, 8192 total
    int v = r >> 7;
    float4 a = ((const float4*)(Wo + (size_t)r*HH))[lane];
    float4 b = ((const float4*)(outW + v*HH))[lane];
    float p = a.x*b.x + a.y*b.y + a.z*b.z + a.w*b.w;
    #pragma unroll
    for (int off = 16; off; off >>= 1) p += __shfl_xor_sync(0xffffffffu, p, off);
    if (lane == 0) g_wf[r] = p;
}

// ---------------- transpose + tf32-round the 6 weight sets: g_Wt[n][k] = W[k][n] ----------------
__global__ void __launch_bounds__(256) k_transpose(const float* __restrict__ mechW,
        const float* __restrict__ Wq, const float* __restrict__ Wk, const float* __restrict__ Wv) {
    extern __shared__ float sm[];     // 128 x 129 floats
    int mat = blockIdx.x >> 6;        // 0..5
    int v   = blockIdx.x & 63;
    const float* src;
    if (mat < 3)       src = mechW + ((size_t)v*NLL + mat)*HH*HH;
    else if (mat == 3) src = Wq + (size_t)v*HH*HH;
    else if (mat == 4) src = Wk + (size_t)v*HH*HH;
    else               src = Wv + (size_t)v*HH*HH;
    float* dst = g_Wt + ((size_t)mat*VV + v)*HH*HH;
    int tid = threadIdx.x;
    for (int idx = tid; idx < HH*HH/4; idx += 256) {
        int k = idx >> 5, c4 = idx & 31;
        float4 w = ((const float4*)src)[idx];
        float* p = sm + k*129 + 4*c4;
        p[0]=w.x; p[1]=w.y; p[2]=w.z; p[3]=w.w;
    }
    __syncthreads();
    for (int idx = tid; idx < HH*HH/4; idx += 256) {
        int n = idx >> 5, k4 = idx & 31;
        int k = 4*k4;
        uint4 u;
        u.x = f2tf32(sm[(k+0)*129 + n]);
        u.y = f2tf32(sm[(k+1)*129 + n]);
        u.z = f2tf32(sm[(k+2)*129 + n]);
        u.w = f2tf32(sm[(k+3)*129 + n]);
        ((uint4*)(dst + n*HH))[k4] = u;
    }
}

// ---------------- fused lagmix + embed + mech x3 + QKV chain via mma.sync tf32 ----------------
// CTA = (row-tile of 64, variable v); 256 threads (8 warps); 2 CTAs/SM.
// Warp w: n-range (w&1)*64..+64, m-range (w>>1)*16..+16.
__global__ void __launch_bounds__(256, 2) k_chain(const float* __restrict__ x,
        const float* __restrict__ mech_b,
        const float* __restrict__ ln_g, const float* __restrict__ ln_b,
        const float* __restrict__ bqv, const float* __restrict__ bkv,
        const float* __restrict__ bvv) {
    extern __shared__ float smf[];
    float* Wsm = smf;                         // 128 x PW floats (also C' staging / x slab)
    float* Zsm = smf + HH*PW;                 // MT x PZ floats
    float* bias_sm = smf + HH*PW + MT*PZ;     // 128
    float* g_sm    = bias_sm + HH;            // 128
    float* be_sm   = g_sm + HH;               // 128
    float* adj_sm  = be_sm + HH;              // 64*11 = 704
    uint32_t* Wu = (uint32_t*)Wsm;
    uint32_t* Zu = (uint32_t*)Zsm;

    int tid  = threadIdx.x;
    int w    = tid >> 5, lane = tid & 31;
    int gid  = lane >> 2, qid = lane & 3;
    int v    = blockIdx.y;
    int r0   = blockIdx.x * MT;
    int n0   = (w & 1) * 64;
    int m0   = (w >> 1) * 16;

    // ======== stage 0: in-CTA lag-mix -> Zsm ========
    {
        float* Xsm = Wsm;                     // 74 x PX floats ~ 20KB, fits in Wsm
        int b  = r0 >> 8;
        int t0 = r0 & 255;
        // load x rows [t0-10 .. t0+63] (zero rows for t<0)
        #pragma unroll
        for (int i = 0; i < 5; i++) {
            int idx = tid + 256*i;            // 74*16 = 1184 float4
            if (idx < 74*16) {
                int row = idx >> 4, c4 = idx & 15;
                int t = t0 - 10 + row;
                float4 val = make_float4(0.f,0.f,0.f,0.f);
                if (t >= 0) val = ((const float4*)(x + ((size_t)b*SS + t)*VV))[c4];
                ((float4*)(Xsm + row*PX))[c4] = val;
            }
        }
        for (int p = tid; p < VV*LL; p += 256) {
            int s = p / LL, l = p % LL;
            adj_sm[p] = g_adj[(s*VV + v)*LL + l];
        }
        __syncthreads();
        // A part: thread = (s = tid&63, mg = tid>>6)
        {
            int s  = tid & 63;
            int mg = tid >> 6;
            float a[LL];
            #pragma unroll
            for (int l = 0; l < LL; l++) a[l] = adj_sm[s*LL + l];
            for (int m = mg; m < MT; m += 4) {
                const float* xcol = Xsm + (m + 10)*PX + s;
                float acc = 0.0f;
                #pragma unroll
                for (int l = 0; l < LL; l++)
                    acc = fmaf(xcol[-l*PX], a[l], acc);
                Zu[m*PZ + s] = f2tf32(acc);
            }
        }
        // Bl part: thread per (m,l)
        for (int idx = tid; idx < MT*LL; idx += 256) {
            int m = idx / LL, l = idx % LL;
            const float* xr = Xsm + (m + 10 - l)*PX;
            float acc = 0.0f;
            #pragma unroll 16
            for (int s = 0; s < VV; s++)
                acc = fmaf(xr[s], adj_sm[s*LL + l], acc);
            Zu[m*PZ + VV + l] = f2tf32(acc);
        }
        // zero pad k-slots 75..79
        for (int idx = tid; idx < MT*5; idx += 256) {
            int m = idx / 5, j = idx % 5;
            Zu[m*PZ + VV + LL + j] = 0u;
        }
        __syncthreads();   // Xsm fully consumed before E^T overwrites Wsm
    }

    // ======== phase -1: embed z = AB @ E ========
    #pragma unroll
    for (int i = 0; i < 10; i++) {
        int idx = tid + 256*i;        // 2560 float4 = 128 rows x 20
        int n = idx / 20, k4 = idx % 20;
        ((float4*)(Wsm + n*PW))[k4] = ((const float4*)g_Et)[idx];
    }
    __syncthreads();
    {
        float acc[4][2][4];
        #pragma unroll
        for (int nt = 0; nt < 4; nt++)
            #pragma unroll
            for (int mt = 0; mt < 2; mt++)
                #pragma unroll
                for (int r = 0; r < 4; r++) acc[nt][mt][r] = 0.0f;
        #pragma unroll 2
        for (int s = 0; s < 10; s++) {
            int k0 = 8*s;
            uint32_t Af[4][4], Bf[2][2];
            #pragma unroll
            for (int nt = 0; nt < 4; nt++) {
                const uint32_t* p = Wu + (n0 + nt*16 + gid)*PW + k0 + qid;
                Af[nt][0] = p[0];
                Af[nt][1] = p[8*PW];
                Af[nt][2] = p[4];
                Af[nt][3] = p[8*PW + 4];
            }
            #pragma unroll
            for (int mt = 0; mt < 2; mt++) {
                const uint32_t* q = Zu + (m0 + mt*8 + gid)*PZ + k0 + qid;
                Bf[mt][0] = q[0];
                Bf[mt][1] = q[4];
            }
            #pragma unroll
            for (int nt = 0; nt < 4; nt++)
                #pragma unroll
                for (int mt = 0; mt < 2; mt++)
                    mma_tf32(acc[nt][mt], Af[nt], Bf[mt]);
        }
        __syncthreads();   // done reading Wsm/Zsm -> stage C'
        #pragma unroll
        for (int nt = 0; nt < 4; nt++) {
            int nb = n0 + nt*16 + gid;
            #pragma unroll
            for (int mt = 0; mt < 2; mt++) {
                int mb = m0 + mt*8 + 2*qid;
                Wsm[ mb   *PW + nb    ] = acc[nt][mt][0];
                Wsm[(mb+1)*PW + nb    ] = acc[nt][mt][1];
                Wsm[ mb   *PW + nb + 8] = acc[nt][mt][2];
                Wsm[(mb+1)*PW + nb + 8] = acc[nt][mt][3];
            }
        }
        __syncthreads();
        // epilogue: z (tf32) into Zsm
        for (int it = 0; it < 8; it++) {
            int m = w + 8*it;
            float4 c = ((const float4*)(Wsm + m*PW))[lane];
            uint4 u; u.x=f2tf32(c.x); u.y=f2tf32(c.y); u.z=f2tf32(c.z); u.w=f2tf32(c.w);
            ((uint4*)(Zu + m*PZ))[lane] = u;
        }
    }

    // ======== phases 0..5 ========
    #pragma unroll 1
    for (int phase = 0; phase < 6; phase++) {
        __syncthreads();
        {
            const float4* src = (const float4*)(g_Wt + ((size_t)phase*VV + v)*HH*HH);
            #pragma unroll
            for (int i = 0; i < 16; i++) {
                int idx = tid + 256*i;
                int n = idx >> 5, k4 = idx & 31;
                ((float4*)(Wsm + n*PW))[k4] = src[idx];
            }
        }
        if (tid < HH) {
            if (phase < 3) {
                bias_sm[tid] = mech_b[((size_t)v*NLL + phase)*HH + tid];
                g_sm[tid]    = ln_g  [((size_t)v*NLL + phase)*HH + tid];
                be_sm[tid]   = ln_b  [((size_t)v*NLL + phase)*HH + tid];
            } else {
                const float* bp = (phase == 3) ? bqv : (phase == 4) ? bkv : bvv;
                bias_sm[tid] = bp[v*HH + tid];
            }
        }
        __syncthreads();

        float acc[4][2][4];
        #pragma unroll
        for (int nt = 0; nt < 4; nt++)
            #pragma unroll
            for (int mt = 0; mt < 2; mt++)
                #pragma unroll
                for (int r = 0; r < 4; r++) acc[nt][mt][r] = 0.0f;

        #pragma unroll 4
        for (int s = 0; s < 16; s++) {
            int k0 = 8*s;
            uint32_t Af[4][4], Bf[2][2];
            #pragma unroll
            for (int nt = 0; nt < 4; nt++) {
                const uint32_t* p = Wu + (n0 + nt*16 + gid)*PW + k0 + qid;
                Af[nt][0] = p[0];
                Af[nt][1] = p[8*PW];
                Af[nt][2] = p[4];
                Af[nt][3] = p[8*PW + 4];
            }
            #pragma unroll
            for (int mt = 0; mt < 2; mt++) {
                const uint32_t* q = Zu + (m0 + mt*8 + gid)*PZ + k0 + qid;
                Bf[mt][0] = q[0];
                Bf[mt][1] = q[4];
            }
            #pragma unroll
            for (int nt = 0; nt < 4; nt++)
                #pragma unroll
                for (int mt = 0; mt < 2; mt++)
                    mma_tf32(acc[nt][mt], Af[nt], Bf[mt]);
        }
        __syncthreads();

        #pragma unroll
        for (int nt = 0; nt < 4; nt++) {
            int nb = n0 + nt*16 + gid;
            #pragma unroll
            for (int mt = 0; mt < 2; mt++) {
                int mb = m0 + mt*8 + 2*qid;
                Wsm[ mb   *PW + nb    ] = acc[nt][mt][0];
                Wsm[(mb+1)*PW + nb    ] = acc[nt][mt][1];
                Wsm[ mb   *PW + nb + 8] = acc[nt][mt][2];
                Wsm[(mb+1)*PW + nb + 8] = acc[nt][mt][3];
            }
        }
        __syncthreads();

        if (phase < 3) {
            for (int it = 0; it < 8; it++) {
                int m = w + 8*it;
                float4 c = ((const float4*)(Wsm + m*PW))[lane];
                float4 b4 = ((const float4*)bias_sm)[lane];
                c.x += b4.x; c.y += b4.y; c.z += b4.z; c.w += b4.w;
                float s  = c.x + c.y + c.z + c.w;
                float ss = c.x*c.x + c.y*c.y + c.z*c.z + c.w*c.w;
                #pragma unroll
                for (int off = 16; off; off >>= 1) {
                    s  += __shfl_xor_sync(0xffffffffu, s,  off);
                    ss += __shfl_xor_sync(0xffffffffu, ss, off);
                }
                float mu   = s * (1.0f/128.0f);
                float var  = ss * (1.0f/128.0f) - mu*mu;
                float rstd = rsqrtf(var + 1e-5f);
                float4 g4  = ((const float4*)g_sm)[lane];
                float4 be4 = ((const float4*)be_sm)[lane];
                const float ic = 0.70710678118654752440f;
                float y;
                uint4 u;
                y = (c.x - mu)*rstd*g4.x + be4.x; y = 0.5f*y*(1.0f + erff(y*ic)); u.x = f2tf32(y);
                y = (c.y - mu)*rstd*g4.y + be4.y; y = 0.5f*y*(1.0f + erff(y*ic)); u.y = f2tf32(y);
                y = (c.z - mu)*rstd*g4.z + be4.z; y = 0.5f*y*(1.0f + erff(y*ic)); u.z = f2tf32(y);
                y = (c.w - mu)*rstd*g4.w + be4.w; y = 0.5f*y*(1.0f + erff(y*ic)); u.w = f2tf32(y);
                ((uint4*)(Zu + m*PZ))[lane] = u;
            }
        } else {
            float* outp = (phase == 3) ? g_q : (phase == 4) ? g_k : g_v;
            for (int it = 0; it < 8; it++) {
                int m = w + 8*it;
                float4 c = ((const float4*)(Wsm + m*PW))[lane];
                float4 b4 = ((const float4*)bias_sm)[lane];
                c.x += b4.x; c.y += b4.y; c.z += b4.z; c.w += b4.w;
                ((float4*)(outp + ((size_t)(r0+m)*VV + v)*HH))[lane] = c;
            }
        }
    }
}

// ---------------- attention via mma.sync tf32, all 8 heads per CTA, fused out head ----------------
__global__ void __launch_bounds__(256, 1) k_attn2(float* __restrict__ out) {
    __shared__ uint32_t Ks[SS*PK];   // 20KB, tf32 bits
    __shared__ uint32_t Vs[SS*PVT];  // 24KB, tf32 bits
    __shared__ float    wfs[HH];
    int bid  = blockIdx.x;
    int v    = bid & (VV-1);
    int b    = bid >> 6;
    int tid  = threadIdx.x;
    int w    = tid >> 5, lane = tid & 31;
    int gid  = lane >> 2, qid = lane & 3;
    const size_t RSTR = (size_t)VV*HH;
    const size_t rowbase = ((size_t)(b*SS)*VV + v)*HH;

    if (tid < HH) wfs[tid] = g_wf[v*HH + tid];
    float bfv = g_bf[v];

    float out_acc[2][2] = {{0.f,0.f},{0.f,0.f}};   // [rep][lo/hi], summed over heads

    #pragma unroll 1
    for (int hh = 0; hh < NHH; hh++) {
        int hbase = hh*DHH;
        __syncthreads();   // protect prior head's Ks/Vs reads (and wfs on first iter)
        {
            const float* kp = g_k + rowbase + (size_t)tid*RSTR + hbase;
            const float* vp = g_v + rowbase + (size_t)tid*RSTR + hbase;
            #pragma unroll
            for (int c4 = 0; c4 < 4; c4++) {
                float4 kv = ((const float4*)kp)[c4];
                float4 vv = ((const float4*)vp)[c4];
                uint32_t* kd = Ks + tid*PK + 4*c4;
                uint32_t* vd = Vs + tid*PVT + 4*c4;
                kd[0] = f2tf32(kv.x); kd[1] = f2tf32(kv.y);
                kd[2] = f2tf32(kv.z); kd[3] = f2tf32(kv.w);
                vd[0] = f2tf32(vv.x); vd[1] = f2tf32(vv.y);
                vd[2] = f2tf32(vv.z); vd[3] = f2tf32(vv.w);
            }
        }
        __syncthreads();

        #pragma unroll 1
        for (int rep = 0; rep < 2; rep++) {
            int q0 = (w + 8*rep) * 16;
            uint32_t Aq[2][4];
            const float* qp = g_q + rowbase + (size_t)q0*RSTR + hbase;
            #pragma unroll
            for (int ks = 0; ks < 2; ks++) {
                int k0 = 8*ks;
                Aq[ks][0] = f2tf32(0.25f*qp[(size_t) gid   *RSTR + k0 + qid    ]);
                Aq[ks][1] = f2tf32(0.25f*qp[(size_t)(gid+8)*RSTR + k0 + qid    ]);
                Aq[ks][2] = f2tf32(0.25f*qp[(size_t) gid   *RSTR + k0 + qid + 4]);
                Aq[ks][3] = f2tf32(0.25f*qp[(size_t)(gid+8)*RSTR + k0 + qid + 4]);
            }
            float sacc[32][4];
            #pragma unroll
            for (int nt = 0; nt < 32; nt++)
                { sacc[nt][0]=0.f; sacc[nt][1]=0.f; sacc[nt][2]=0.f; sacc[nt][3]=0.f; }
            #pragma unroll
            for (int nt = 0; nt < 32; nt++) {
                #pragma unroll
                for (int ks = 0; ks < 2; ks++) {
                    uint32_t Bf[2];
                    const uint32_t* kp2 = Ks + (nt*8 + gid)*PK + 8*ks + qid;
                    Bf[0] = kp2[0];
                    Bf[1] = kp2[4];
                    mma_tf32(sacc[nt], Aq[ks], Bf);
                }
            }
            float m0 = -1e30f, m1 = -1e30f;
            #pragma unroll
            for (int nt = 0; nt < 32; nt++) {
                m0 = fmaxf(m0, fmaxf(sacc[nt][0], sacc[nt][1]));
                m1 = fmaxf(m1, fmaxf(sacc[nt][2], sacc[nt][3]));
            }
            m0 = fmaxf(m0, __shfl_xor_sync(0xffffffffu, m0, 1));
            m0 = fmaxf(m0, __shfl_xor_sync(0xffffffffu, m0, 2));
            m1 = fmaxf(m1, __shfl_xor_sync(0xffffffffu, m1, 1));
            m1 = fmaxf(m1, __shfl_xor_sync(0xffffffffu, m1, 2));
            float s0 = 0.f, s1 = 0.f;
            uint32_t* su = (uint32_t*)sacc;
            #pragma unroll
            for (int nt = 0; nt < 32; nt++) {
                float e0 = __expf(sacc[nt][0] - m0);
                float e1 = __expf(sacc[nt][1] - m0);
                float e2 = __expf(sacc[nt][2] - m1);
                float e3 = __expf(sacc[nt][3] - m1);
                s0 += e0 + e1; s1 += e2 + e3;
                su[4*nt+0] = f2tf32(e0); su[4*nt+1] = f2tf32(e1);
                su[4*nt+2] = f2tf32(e2); su[4*nt+3] = f2tf32(e3);
            }
            s0 += __shfl_xor_sync(0xffffffffu, s0, 1);
            s0 += __shfl_xor_sync(0xffffffffu, s0, 2);
            s1 += __shfl_xor_sync(0xffffffffu, s1, 1);
            s1 += __shfl_xor_sync(0xffffffffu, s1, 2);
            float inv0 = 1.0f/s0, inv1 = 1.0f/s1;
            float oacc[2][4];
            oacc[0][0]=0.f; oacc[0][1]=0.f; oacc[0][2]=0.f; oacc[0][3]=0.f;
            oacc[1][0]=0.f; oacc[1][1]=0.f; oacc[1][2]=0.f; oacc[1][3]=0.f;
            int src_lo = (lane & ~3) | (qid >> 1);
            int src_hi = src_lo + 2;
            int psel   = qid & 1;
            #pragma unroll
            for (int kc = 0; kc < 32; kc++) {
                uint32_t aP[4];
                uint32_t e0 = __shfl_sync(0xffffffffu, su[4*kc+0], src_lo);
                uint32_t e1 = __shfl_sync(0xffffffffu, su[4*kc+1], src_lo);
                aP[0] = psel ? e1 : e0;
                uint32_t g0 = __shfl_sync(0xffffffffu, su[4*kc+2], src_lo);
                uint32_t g1 = __shfl_sync(0xffffffffu, su[4*kc+3], src_lo);
                aP[1] = psel ? g1 : g0;
                uint32_t h0 = __shfl_sync(0xffffffffu, su[4*kc+0], src_hi);
                uint32_t h1 = __shfl_sync(0xffffffffu, su[4*kc+1], src_hi);
                aP[2] = psel ? h1 : h0;
                uint32_t i0 = __shfl_sync(0xffffffffu, su[4*kc+2], src_hi);
                uint32_t i1 = __shfl_sync(0xffffffffu, su[4*kc+3], src_hi);
                aP[3] = psel ? i1 : i0;
                #pragma unroll
                for (int nt2 = 0; nt2 < 2; nt2++) {
                    uint32_t Bv[2];
                    const uint32_t* vp2 = Vs + (kc*8 + qid)*PVT + nt2*8 + gid;
                    Bv[0] = vp2[0];
                    Bv[1] = vp2[4*PVT];
                    mma_tf32(oacc[nt2], aP, Bv);
                }
            }
            // ---- fused output head: partial = (o . wf[hbase..]) per row, accum over heads ----
            float plo = 0.f, phi = 0.f;
            #pragma unroll
            for (int nt2 = 0; nt2 < 2; nt2++) {
                float w0 = wfs[hbase + nt2*8 + 2*qid];
                float w1 = wfs[hbase + nt2*8 + 2*qid + 1];
                plo = fmaf(oacc[nt2][0], w0, fmaf(oacc[nt2][1], w1, plo));
                phi = fmaf(oacc[nt2][2], w0, fmaf(oacc[nt2][3], w1, phi));
            }
            out_acc[rep][0] += plo*inv0;
            out_acc[rep][1] += phi*inv1;
        }
    }

    // ---- final quad reduce + single store (covers every (row, v) exactly once) ----
    #pragma unroll
    for (int rep = 0; rep < 2; rep++) {
        float plo = out_acc[rep][0], phi = out_acc[rep][1];
        plo += __shfl_xor_sync(0xffffffffu, plo, 1);
        plo += __shfl_xor_sync(0xffffffffu, plo, 2);
        phi += __shfl_xor_sync(0xffffffffu, phi, 1);
        phi += __shfl_xor_sync(0xffffffffu, phi, 2);
        if (qid == 0) {
            int q0 = (w + 8*rep) * 16;
            out[(size_t)(b*SS + q0 + gid    )*VV + v] = plo + bfv;
            out[(size_t)(b*SS + q0 + gid + 8)*VV + v] = phi + bfv;
        }
    }
}

// ---------------- launch ----------------
extern "C" void kernel_launch(void* const* d_in, const int* in_sizes, int n_in,
                              void* d_out, int out_size) {
    (void)in_sizes; (void)n_in; (void)out_size;
    const float* x        = (const float*)d_in[0];
    const float* adjl     = (const float*)d_in[1];
    const float* var_emb  = (const float*)d_in[2];
    const float* temp_emb = (const float*)d_in[3];
    const float* mech_W   = (const float*)d_in[4];
    const float* mech_b   = (const float*)d_in[5];
    const float* ln_g     = (const float*)d_in[6];
    const float* ln_b     = (const float*)d_in[7];
    const float* Wq       = (const float*)d_in[8];
    const float* Wk       = (const float*)d_in[9];
    const float* Wv       = (const float*)d_in[10];
    const float* Wo       = (const float*)d_in[11];
    const float* bq       = (const float*)d_in[12];
    const float* bk       = (const float*)d_in[13];
    const float* bv       = (const float*)d_in[14];
    const float* bo       = (const float*)d_in[15];
    const float* outW     = (const float*)d_in[16];
    const float* outb     = (const float*)d_in[17];
    float* out = (float*)d_out;

    const int SMEM_TRANS = HH*129*4;
    const int SMEM_CHAIN = (HH*PW + MT*PZ + 3*HH + VV*LL)*4;   // 107776
    cudaFuncSetAttribute(k_transpose, cudaFuncAttributeMaxDynamicSharedMemorySize, SMEM_TRANS);
    cudaFuncSetAttribute(k_chain,     cudaFuncAttributeMaxDynamicSharedMemorySize, SMEM_CHAIN);

    const int N_PREP = VV*VV*LL + HH*KAB + VV;   // 55360
    k_prep<<<(N_PREP + 255)/256, 256>>>(adjl, var_emb, temp_emb, outW, bo, outb);
    k_prepwf<<<VV*HH/8, 256>>>(Wo, outW);
    k_transpose<<<6*VV, 256, SMEM_TRANS>>>(mech_W, Wq, Wk, Wv);

    dim3 gchain(BS/MT, VV);   // (16, 64)
    k_chain<<<gchain, 256, SMEM_CHAIN>>>(x, mech_b, ln_g, ln_b, bq, bk, bv);

    k_attn2<<<BB*VV, 256>>>(out);
}